// round 10
// baseline (speedup 1.0000x reference)
#include <cuda_runtime.h>
#include <cuda_bf16.h>
#include <math_constants.h>
#include <cstdint>

// ---------------- problem constants ----------------
#define NN      20000
#define EE      320000
#define TT      12
#define IN_DIM  128
#define HID     256
#define OUTD    128
#define HEADS   4
#define NEG     0.2f
#define NCHAIN  4

// packed bf16 weight tables, layout [M][K/2] u32
#define WB1 0
#define WB2 16384
#define WB3 49152
#define WBTOT 65536

// ---------------- device scratch (per-chain) ----------------
__device__ float4   g_hw4[NCHAIN][(size_t)NN * HID / 4];
__device__ float4   g_x4 [NCHAIN][(size_t)NN * HID / 4];
__device__ float4   g_w4 [NCHAIN][EE];
__device__ float    g_as [NCHAIN][NN * HEADS];
__device__ float    g_ad [NCHAIN][NN * HEADS];
__device__ uint32_t g_wbh[WBTOT];
__device__ uint32_t g_wbl[WBTOT];
__device__ int      g_src [EE];
__device__ int      g_dst [EE];
__device__ int      g_cnt [NN];
__device__ int      g_roff[NN + 1];
__device__ int      g_cur [NN];
__device__ int      g_eid [EE];

// ---------------- edge-index dtype detect + normalize (+ cnt zero) ---------
__global__ void detconv_k(const void* ei) {
    __shared__ int is64;
    if (threadIdx.x == 0) {
        int bad = 0;
        const long long* p = (const long long*)ei;
        for (int i = 0; i < 256; i++) {
            long long v = p[i];
            if (v < 0 || v >= NN) { bad = 1; break; }
        }
        is64 = bad ? 0 : 1;
    }
    __syncthreads();
    int i = blockIdx.x * blockDim.x + threadIdx.x;
    if (i < NN) g_cnt[i] = 0;
    if (i >= EE) return;
    if (is64) {
        const long long* p = (const long long*)ei;
        g_src[i] = (int)p[i];
        g_dst[i] = (int)p[EE + i];
    } else {
        const int* p = (const int*)ei;
        g_src[i] = p[i];
        g_dst[i] = p[EE + i];
    }
}

// ---------------- CSR build (by dst) ----------------
__global__ void hist_k(const int* __restrict__ dst, int* __restrict__ cnt) {
    int e = blockIdx.x * blockDim.x + threadIdx.x;
    if (e < EE) atomicAdd(&cnt[dst[e]], 1);
}

__global__ void scan_k(const int* __restrict__ cnt, int* __restrict__ roff,
                       int* __restrict__ cur) {
    __shared__ int part[1024];
    const int chunk = (NN + 1023) / 1024;
    int t = threadIdx.x;
    int lo = t * chunk;
    int hi = lo + chunk; if (hi > NN) hi = NN;
    int s = 0;
    for (int i = lo; i < hi; i++) s += cnt[i];
    part[t] = s;
    __syncthreads();
    for (int o = 1; o < 1024; o <<= 1) {
        int v = (t >= o) ? part[t - o] : 0;
        __syncthreads();
        part[t] += v;
        __syncthreads();
    }
    int base = (t == 0) ? 0 : part[t - 1];
    for (int i = lo; i < hi; i++) {
        roff[i] = base;
        cur[i] = base;
        base += cnt[i];
    }
    if (t == 1023) roff[NN] = base;
}

__global__ void scatter_k(const int* __restrict__ dst, int* __restrict__ cur,
                          int* __restrict__ eid) {
    int e = blockIdx.x * blockDim.x + threadIdx.x;
    if (e >= EE) return;
    int p = atomicAdd(&cur[dst[e]], 1);
    eid[p] = e;
}

// ---------------- bf16 helpers ----------------
__device__ __forceinline__ void split2_bf16(float x, float y,
                                            uint32_t& h, uint32_t& l) {
    __nv_bfloat162 hh = __floats2bfloat162_rn(x, y);
    h = *(uint32_t*)&hh;
    float rx = x - __bfloat162float(hh.x);
    float ry = y - __bfloat162float(hh.y);
    __nv_bfloat162 ll = __floats2bfloat162_rn(rx, ry);
    l = *(uint32_t*)&ll;
}

__device__ __forceinline__ void mma_bf16(float* c, uint32_t a0, uint32_t a1,
                                         uint32_t a2, uint32_t a3,
                                         uint32_t b0, uint32_t b1) {
    asm volatile(
        "mma.sync.aligned.m16n8k16.row.col.f32.bf16.bf16.f32 "
        "{%0,%1,%2,%3}, {%4,%5,%6,%7}, {%8,%9}, {%0,%1,%2,%3};"
        : "+f"(c[0]), "+f"(c[1]), "+f"(c[2]), "+f"(c[3])
        : "r"(a0), "r"(a1), "r"(a2), "r"(a3), "r"(b0), "r"(b1));
}

__device__ __forceinline__ uint32_t smem_u32(const void* p) {
    uint32_t a;
    asm("{ .reg .u64 t; cvta.to.shared.u64 t, %1; cvt.u32.u64 %0, t; }"
        : "=r"(a) : "l"(p));
    return a;
}

// ---------------- one-time weight split: [K][M] f32 -> [M][K/2] bf16x2 ------
__global__ void split_wb_k(const float* __restrict__ W1,
                           const float* __restrict__ W2,
                           const float* __restrict__ W3,
                           uint32_t* __restrict__ wbh,
                           uint32_t* __restrict__ wbl) {
    int i = blockIdx.x * blockDim.x + threadIdx.x;
    if (i >= WBTOT) return;
    const float* W; int K, M, idx;
    if (i < WB2)      { W = W1; K = IN_DIM; M = HID;  idx = i; }
    else if (i < WB3) { W = W2; K = HID;    M = HID;  idx = i - WB2; }
    else              { W = W3; K = HID;    M = OUTD; idx = i - WB3; }
    int kb2 = K / 2;
    int n = idx / kb2;
    int j = idx - n * kb2;
    float x = W[(size_t)(2 * j) * M + n];
    float y = W[(size_t)(2 * j + 1) * M + n];
    uint32_t h, l;
    split2_bf16(x, y, h, l);
    wbh[i] = h;
    wbl[i] = l;
}

// ---------------- GEMM: C[N,M] = A[N,K](lda) * B[K,M], 3xBF16 ----------------
// BM=128, BN=128, BK=32, 256 threads, warp tile 64x32, 2 blocks/SM.
// cp.async double-buffered: A staged raw f32 (split to bf16 smem from smem),
// B pre-split bf16x2 hi/lo loaded directly. GMEM latency overlapped.
// smem (u32): Ast[2]=2*4608, Ah/Al=2*2560, Bh/Bl[2]=4*2560 -> 24576 u32 = 96KB
#define AST0 0
#define AST1 4608
#define AHOF 9216
#define ALOF 11776
#define BH0  14336
#define BL0  16896
#define BH1  19456
#define BL1  22016
#define GEMM_SMEM (24576 * 4)
__global__ __launch_bounds__(256, 2)
void gemm_tc_k(const float* __restrict__ A, int lda,
               const uint32_t* __restrict__ Bhg,
               const uint32_t* __restrict__ Blg,
               float* __restrict__ C,
               int Nrows, int K, int M) {
    extern __shared__ uint32_t smem[];
    const uint32_t sbase = smem_u32(smem);

    const int tid = threadIdx.x;
    const int wid = tid >> 5;
    const int lane = tid & 31;
    const int gid = lane >> 2;
    const int t4 = lane & 3;
    const int rm = blockIdx.y * 128;
    const int cn = blockIdx.x * 128;
    const int wm = (wid & 1) * 64;
    const int wn = (wid >> 1) * 32;
    const int KB2 = K >> 1;

    float acc[4][4][4];
#pragma unroll
    for (int i = 0; i < 4; i++)
#pragma unroll
        for (int j = 0; j < 4; j++)
#pragma unroll
            for (int q = 0; q < 4; q++) acc[i][j][q] = 0.f;

    const int ar = tid >> 3;        // A: row base 0..31
    const int af = tid & 7;         // A: float4 slot
    const int bn2 = tid >> 1;       // B: n row 0..127
    const int bq = (tid & 1) * 2;   // B: uint4 slot base

    auto issue = [&](int buf, int k0) {
        const int astoff = buf ? AST1 : AST0;
#pragma unroll
        for (int l = 0; l < 4; l++) {
            int row = ar + 32 * l;
            int grow = rm + row;
            int ok = (grow < Nrows);
            uint32_t sa = sbase + (uint32_t)(astoff + row * 36 + af * 4) * 4;
            const float* g = A + (size_t)(ok ? grow : 0) * lda + k0 + af * 4;
            int sz = ok ? 16 : 0;
            asm volatile("cp.async.ca.shared.global [%0], [%1], 16, %2;\n"
                         :: "r"(sa), "l"(g), "r"(sz));
        }
        const int bhoff = buf ? BH1 : BH0;
        const int bloff = buf ? BL1 : BL0;
#pragma unroll
        for (int u = 0; u < 2; u++) {
            int q = bq + u;
            size_t go = (size_t)(cn + bn2) * KB2 + (k0 >> 1) + q * 4;
            uint32_t sh = sbase + (uint32_t)(bhoff + bn2 * 20 + q * 4) * 4;
            uint32_t sl = sbase + (uint32_t)(bloff + bn2 * 20 + q * 4) * 4;
            asm volatile("cp.async.ca.shared.global [%0], [%1], 16;\n"
                         :: "r"(sh), "l"(Bhg + go));
            asm volatile("cp.async.ca.shared.global [%0], [%1], 16;\n"
                         :: "r"(sl), "l"(Blg + go));
        }
        asm volatile("cp.async.commit_group;\n");
    };

    uint32_t (*Ah)[20] = (uint32_t(*)[20])(smem + AHOF);
    uint32_t (*Al)[20] = (uint32_t(*)[20])(smem + ALOF);

    const int niter = K >> 5;
    issue(0, 0);

    for (int ki = 0; ki < niter; ki++) {
        const int buf = ki & 1;
        asm volatile("cp.async.wait_group 0;\n");
        __syncthreads();   // staged tile visible; prior MMA reads complete
        if (ki + 1 < niter) issue(buf ^ 1, (ki + 1) * 32);

        // split A staging (f32) -> bf16 hi/lo tiles
        const float* Ast = (const float*)(smem + (buf ? AST1 : AST0));
#pragma unroll
        for (int l = 0; l < 4; l++) {
            int row = ar + 32 * l;
            float4 v = *(const float4*)(Ast + row * 36 + af * 4);
            uint32_t h0, l0, h1, l1;
            split2_bf16(v.x, v.y, h0, l0);
            split2_bf16(v.z, v.w, h1, l1);
            Ah[row][af * 2] = h0; Ah[row][af * 2 + 1] = h1;
            Al[row][af * 2] = l0; Al[row][af * 2 + 1] = l1;
        }
        __syncthreads();

        const uint32_t (*Bh)[20] = (const uint32_t(*)[20])(smem + (buf ? BH1 : BH0));
        const uint32_t (*Bl)[20] = (const uint32_t(*)[20])(smem + (buf ? BL1 : BL0));
#pragma unroll
        for (int s = 0; s < 2; s++) {
            const int jb = s * 8;
            uint32_t ah[4][4], al[4][4], bh[4][2], bl[4][2];
#pragma unroll
            for (int ma = 0; ma < 4; ma++) {
                int m = wm + ma * 16;
                ah[ma][0] = Ah[m + gid][jb + t4];
                ah[ma][1] = Ah[m + gid + 8][jb + t4];
                ah[ma][2] = Ah[m + gid][jb + t4 + 4];
                ah[ma][3] = Ah[m + gid + 8][jb + t4 + 4];
                al[ma][0] = Al[m + gid][jb + t4];
                al[ma][1] = Al[m + gid + 8][jb + t4];
                al[ma][2] = Al[m + gid][jb + t4 + 4];
                al[ma][3] = Al[m + gid + 8][jb + t4 + 4];
            }
#pragma unroll
            for (int nb = 0; nb < 4; nb++) {
                int col = wn + nb * 8 + gid;
                bh[nb][0] = Bh[col][jb + t4];
                bh[nb][1] = Bh[col][jb + t4 + 4];
                bl[nb][0] = Bl[col][jb + t4];
                bl[nb][1] = Bl[col][jb + t4 + 4];
            }
#pragma unroll
            for (int ma = 0; ma < 4; ma++)
#pragma unroll
                for (int nb = 0; nb < 4; nb++) {
                    float* c = acc[ma][nb];
                    mma_bf16(c, ah[ma][0], ah[ma][1], ah[ma][2], ah[ma][3],
                             bh[nb][0], bh[nb][1]);
                    mma_bf16(c, ah[ma][0], ah[ma][1], ah[ma][2], ah[ma][3],
                             bl[nb][0], bl[nb][1]);
                    mma_bf16(c, al[ma][0], al[ma][1], al[ma][2], al[ma][3],
                             bh[nb][0], bh[nb][1]);
                }
        }
        __syncthreads();
    }

#pragma unroll
    for (int ma = 0; ma < 4; ma++) {
        int r0 = rm + wm + ma * 16 + gid;
        int r1 = r0 + 8;
#pragma unroll
        for (int nb = 0; nb < 4; nb++) {
            int col = cn + wn + nb * 8 + 2 * t4;
            if (r0 < Nrows)
                *(float2*)(C + (size_t)r0 * M + col) =
                    make_float2(acc[ma][nb][0], acc[ma][nb][1]);
            if (r1 < Nrows)
                *(float2*)(C + (size_t)r1 * M + col) =
                    make_float2(acc[ma][nb][2], acc[ma][nb][3]);
        }
    }
}

// ---------------- per-node attention logits (warp per node) ----------------
template<int M>
__global__ void node_prep_k(const float* __restrict__ hw,
                            const float* __restrict__ a_src,
                            const float* __restrict__ a_dst,
                            float* __restrict__ as_, float* __restrict__ ad_) {
    constexpr int NC = M / 32;
    constexpr int C = M / 4;
    int warp = (blockIdx.x * blockDim.x + threadIdx.x) >> 5;
    int lane = threadIdx.x & 31;
    if (warp >= NN) return;
    int g = lane >> 3;
    int cb = (lane & 7) * NC;
    const float* hp = hw + (size_t)warp * M + g * C + cb;
    const float* sp = a_src + g * C + cb;
    const float* dp = a_dst + g * C + cb;
    float vs = 0.f, vd = 0.f;
#pragma unroll
    for (int j = 0; j < NC; j++) {
        float x = hp[j];
        vs += x * sp[j];
        vd += x * dp[j];
    }
#pragma unroll
    for (int o = 1; o < 8; o <<= 1) {
        vs += __shfl_xor_sync(0xffffffffu, vs, o);
        vd += __shfl_xor_sync(0xffffffffu, vd, o);
    }
    if ((lane & 7) == 0) {
        as_[warp * 4 + g] = vs;
        ad_[warp * 4 + g] = vd;
    }
}

// ---------------- fused softmax + gather aggregation (warp per node) -------
template<int M, int DORELU>
__global__ void gat_node_k(const int* __restrict__ roff,
                           const int* __restrict__ eid,
                           const int* __restrict__ src,
                           const float* __restrict__ as_,
                           const float* __restrict__ ad_,
                           const float* __restrict__ hw,
                           float* __restrict__ wbuf,
                           const float* __restrict__ bias,
                           float* __restrict__ out, int ostride) {
    constexpr int NC = M / 32;
    int warp = (blockIdx.x * blockDim.x + threadIdx.x) >> 5;
    int lane = threadIdx.x & 31;
    if (warp >= NN) return;
    const int n = warp;
    const int beg = roff[n], end = roff[n + 1];
    const int h = lane & 3, slot = lane >> 2;

    float adv = ad_[n * 4 + h];
    float mx = -CUDART_INF_F;
    for (int i = beg + slot; i < end; i += 8) {
        int s = src[eid[i]];
        float v = as_[s * 4 + h] + adv;
        v = (v > 0.f) ? v : NEG * v;
        wbuf[(size_t)i * 4 + h] = v;
        mx = fmaxf(mx, v);
    }
    mx = fmaxf(mx, __shfl_xor_sync(0xffffffffu, mx, 4));
    mx = fmaxf(mx, __shfl_xor_sync(0xffffffffu, mx, 8));
    mx = fmaxf(mx, __shfl_xor_sync(0xffffffffu, mx, 16));

    float den = 0.f;
    for (int i = beg + slot; i < end; i += 8) {
        float w = expf(wbuf[(size_t)i * 4 + h] - mx);
        wbuf[(size_t)i * 4 + h] = w;
        den += w;
    }
    den += __shfl_xor_sync(0xffffffffu, den, 4);
    den += __shfl_xor_sync(0xffffffffu, den, 8);
    den += __shfl_xor_sync(0xffffffffu, den, 16);
    den += 1e-16f;
    __threadfence_block();
    __syncwarp();

    const int hh = lane >> 3;
    float dinv = 1.0f / __shfl_sync(0xffffffffu, den, hh);
    float acc[NC];
#pragma unroll
    for (int j = 0; j < NC; j++) acc[j] = 0.f;
    const int colbase = lane * NC;
    for (int i = beg; i < end; i++) {
        int s = src[eid[i]];
        float4 w4 = *(const float4*)(wbuf + (size_t)i * 4);
        float wv = (hh == 0) ? w4.x : (hh == 1) ? w4.y : (hh == 2) ? w4.z : w4.w;
        float a = wv * dinv;
        const float* hp = hw + (size_t)s * M + colbase;
#pragma unroll
        for (int j = 0; j < NC; j += 4) {
            float4 v = *(const float4*)(hp + j);
            acc[j + 0] += a * v.x;
            acc[j + 1] += a * v.y;
            acc[j + 2] += a * v.z;
            acc[j + 3] += a * v.w;
        }
    }
    float* op = out + (size_t)n * ostride + colbase;
    const float* bp = bias + colbase;
#pragma unroll
    for (int j = 0; j < NC; j++) {
        float v = acc[j] + bp[j];
        if (DORELU) v = fmaxf(v, 0.f);
        op[j] = v;
    }
}

// ---------------- host orchestration ----------------
extern "C" void kernel_launch(void* const* d_in, const int* in_sizes, int n_in,
                              void* d_out, int out_size) {
    const float* x  = (const float*)d_in[0];
    const void*  ei = d_in[1];
    const float* asrc[3] = {(const float*)d_in[3], (const float*)d_in[7],
                            (const float*)d_in[11]};
    const float* adst[3] = {(const float*)d_in[4], (const float*)d_in[8],
                            (const float*)d_in[12]};
    const float* bias[3] = {(const float*)d_in[5], (const float*)d_in[9],
                            (const float*)d_in[13]};
    float* out = (float*)d_out;

    static cudaStream_t ss[NCHAIN - 1];
    static cudaEvent_t ev_fork, ev_join[NCHAIN - 1];
    static bool inited = false;
    if (!inited) {
        inited = true;
        for (int i = 0; i < NCHAIN - 1; i++) {
            cudaStreamCreateWithFlags(&ss[i], cudaStreamNonBlocking);
            cudaEventCreateWithFlags(&ev_join[i], cudaEventDisableTiming);
        }
        cudaEventCreateWithFlags(&ev_fork, cudaEventDisableTiming);
        cudaFuncSetAttribute(gemm_tc_k,
                             cudaFuncAttributeMaxDynamicSharedMemorySize,
                             GEMM_SMEM);
    }

    float *p_hw[NCHAIN], *p_x[NCHAIN], *p_w[NCHAIN], *p_as[NCHAIN], *p_ad[NCHAIN];
    {
        float4 *b_hw, *b_x, *b_w; float *b_as, *b_ad;
        cudaGetSymbolAddress((void**)&b_hw, g_hw4);
        cudaGetSymbolAddress((void**)&b_x, g_x4);
        cudaGetSymbolAddress((void**)&b_w, g_w4);
        cudaGetSymbolAddress((void**)&b_as, g_as);
        cudaGetSymbolAddress((void**)&b_ad, g_ad);
        for (int c = 0; c < NCHAIN; c++) {
            p_hw[c] = (float*)(b_hw + (size_t)c * (NN * HID / 4));
            p_x[c]  = (float*)(b_x  + (size_t)c * (NN * HID / 4));
            p_w[c]  = (float*)(b_w  + (size_t)c * EE);
            p_as[c] = b_as + (size_t)c * (NN * HEADS);
            p_ad[c] = b_ad + (size_t)c * (NN * HEADS);
        }
    }
    uint32_t *p_wbh, *p_wbl;
    cudaGetSymbolAddress((void**)&p_wbh, g_wbh);
    cudaGetSymbolAddress((void**)&p_wbl, g_wbl);
    int *p_src, *p_dst, *p_cnt, *p_roff, *p_cur, *p_eid;
    cudaGetSymbolAddress((void**)&p_src, g_src);
    cudaGetSymbolAddress((void**)&p_dst, g_dst);
    cudaGetSymbolAddress((void**)&p_cnt, g_cnt);
    cudaGetSymbolAddress((void**)&p_roff, g_roff);
    cudaGetSymbolAddress((void**)&p_cur, g_cur);
    cudaGetSymbolAddress((void**)&p_eid, g_eid);

    const uint32_t* wbh[3] = {p_wbh + WB1, p_wbh + WB2, p_wbh + WB3};
    const uint32_t* wbl[3] = {p_wbl + WB1, p_wbl + WB2, p_wbl + WB3};

    // --- preprocessing on stream 0: 5 launches; launch #6 = first gemm ---
    detconv_k<<<(EE + 255) / 256, 256>>>(ei);                        // 1
    hist_k<<<(EE + 255) / 256, 256>>>(p_dst, p_cnt);                 // 2
    scan_k<<<1, 1024>>>(p_cnt, p_roff, p_cur);                       // 3
    scatter_k<<<(EE + 255) / 256, 256>>>(p_dst, p_cur, p_eid);       // 4
    split_wb_k<<<(WBTOT + 255) / 256, 256>>>((const float*)d_in[2],
                                             (const float*)d_in[6],
                                             (const float*)d_in[10],
                                             p_wbh, p_wbl);          // 5

    cudaEventRecord(ev_fork, 0);
    for (int i = 0; i < NCHAIN - 1; i++)
        cudaStreamWaitEvent(ss[i], ev_fork, 0);

    const int npblk = (NN * 32 + 255) / 256;
    const int rowblk = (NN + 127) / 128;

    for (int c = 0; c < NCHAIN; c++) {
        cudaStream_t st = (c == 0) ? (cudaStream_t)0 : ss[c - 1];
        for (int t = c; t < TT; t += NCHAIN) {
            // layer 1
            {
                dim3 gg(HID / 128, rowblk);
                gemm_tc_k<<<gg, 256, GEMM_SMEM, st>>>(
                    x + (size_t)t * IN_DIM, TT * IN_DIM, wbh[0], wbl[0],
                    p_hw[c], NN, IN_DIM, HID);
                node_prep_k<HID><<<npblk, 256, 0, st>>>(p_hw[c], asrc[0],
                                                        adst[0], p_as[c], p_ad[c]);
                gat_node_k<HID, 1><<<npblk, 256, 0, st>>>(
                    p_roff, p_eid, p_src, p_as[c], p_ad[c], p_hw[c], p_w[c],
                    bias[0], p_x[c], HID);
            }
            // layer 2
            {
                dim3 gg(HID / 128, rowblk);
                gemm_tc_k<<<gg, 256, GEMM_SMEM, st>>>(
                    p_x[c], HID, wbh[1], wbl[1], p_hw[c], NN, HID, HID);
                node_prep_k<HID><<<npblk, 256, 0, st>>>(p_hw[c], asrc[1],
                                                        adst[1], p_as[c], p_ad[c]);
                gat_node_k<HID, 1><<<npblk, 256, 0, st>>>(
                    p_roff, p_eid, p_src, p_as[c], p_ad[c], p_hw[c], p_w[c],
                    bias[1], p_x[c], HID);
            }
            // layer 3
            {
                dim3 gg(OUTD / 128, rowblk);
                gemm_tc_k<<<gg, 256, GEMM_SMEM, st>>>(
                    p_x[c], HID, wbh[2], wbl[2], p_hw[c], NN, HID, OUTD);
                node_prep_k<OUTD><<<npblk, 256, 0, st>>>(p_hw[c], asrc[2],
                                                         adst[2], p_as[c], p_ad[c]);
                gat_node_k<OUTD, 0><<<npblk, 256, 0, st>>>(
                    p_roff, p_eid, p_src, p_as[c], p_ad[c], p_hw[c], p_w[c],
                    bias[2], out + (size_t)t * OUTD, TT * OUTD);
            }
        }
    }

    for (int i = 0; i < NCHAIN - 1; i++) {
        cudaEventRecord(ev_join[i], ss[i]);
        cudaStreamWaitEvent((cudaStream_t)0, ev_join[i], 0);
    }
}

// round 12
// speedup vs baseline: 1.2949x; 1.2949x over previous
#include <cuda_runtime.h>
#include <cuda_bf16.h>
#include <math_constants.h>
#include <cstdint>

// ---------------- problem constants ----------------
#define NN      20000
#define EE      320000
#define TT      12
#define IN_DIM  128
#define HID     256
#define OUTD    128
#define HEADS   4
#define NEG     0.2f
#define NCHAIN  4            // 3 extra streams max (R11: more trips alloc guard)

// packed bf16 weight tables, layout [M][K/2] u32
#define WB1 0
#define WB2 16384
#define WB3 49152
#define WBTOT 65536

// ---------------- device scratch (per-chain) ----------------
__device__ float4   g_hw4[NCHAIN][(size_t)NN * HID / 4];
__device__ float4   g_x4 [NCHAIN][(size_t)NN * HID / 4];
__device__ float4   g_w4 [NCHAIN][EE];
__device__ float    g_asd[NCHAIN][2 * NN * HEADS];   // as | ad contiguous
__device__ uint32_t g_wbh[WBTOT];
__device__ uint32_t g_wbl[WBTOT];
__device__ int      g_src [EE];
__device__ int      g_dst [EE];
__device__ int      g_cnt [NN];
__device__ int      g_roff[NN + 1];
__device__ int      g_cur [NN];
__device__ int      g_srcp[EE];     // CSR-ordered source ids (replaces eid)

// ---------------- edge-index dtype detect + normalize (+ cnt zero) ---------
__global__ void detconv_k(const void* ei) {
    __shared__ int is64;
    if (threadIdx.x == 0) {
        int bad = 0;
        const long long* p = (const long long*)ei;
        for (int i = 0; i < 256; i++) {
            long long v = p[i];
            if (v < 0 || v >= NN) { bad = 1; break; }
        }
        is64 = bad ? 0 : 1;
    }
    __syncthreads();
    int i = blockIdx.x * blockDim.x + threadIdx.x;
    if (i < NN) g_cnt[i] = 0;
    if (i >= EE) return;
    if (is64) {
        const long long* p = (const long long*)ei;
        g_src[i] = (int)p[i];
        g_dst[i] = (int)p[EE + i];
    } else {
        const int* p = (const int*)ei;
        g_src[i] = p[i];
        g_dst[i] = p[EE + i];
    }
}

// ---------------- CSR build (by dst) ----------------
__global__ void hist_k(const int* __restrict__ dst, int* __restrict__ cnt) {
    int e = blockIdx.x * blockDim.x + threadIdx.x;
    if (e < EE) atomicAdd(&cnt[dst[e]], 1);
}

__global__ void scan_k(const int* __restrict__ cnt, int* __restrict__ roff,
                       int* __restrict__ cur) {
    __shared__ int part[1024];
    const int chunk = (NN + 1023) / 1024;
    int t = threadIdx.x;
    int lo = t * chunk;
    int hi = lo + chunk; if (hi > NN) hi = NN;
    int s = 0;
    for (int i = lo; i < hi; i++) s += cnt[i];
    part[t] = s;
    __syncthreads();
    for (int o = 1; o < 1024; o <<= 1) {
        int v = (t >= o) ? part[t - o] : 0;
        __syncthreads();
        part[t] += v;
        __syncthreads();
    }
    int base = (t == 0) ? 0 : part[t - 1];
    for (int i = lo; i < hi; i++) {
        roff[i] = base;
        cur[i] = base;
        base += cnt[i];
    }
    if (t == 1023) roff[NN] = base;
}

// scatter permuted src directly (no eid indirection downstream)
__global__ void scatter_k(const int* __restrict__ src,
                          const int* __restrict__ dst,
                          int* __restrict__ cur, int* __restrict__ srcp) {
    int e = blockIdx.x * blockDim.x + threadIdx.x;
    if (e >= EE) return;
    int p = atomicAdd(&cur[dst[e]], 1);
    srcp[p] = src[e];
}

// ---------------- bf16 helpers ----------------
__device__ __forceinline__ void split2_bf16(float x, float y,
                                            uint32_t& h, uint32_t& l) {
    __nv_bfloat162 hh = __floats2bfloat162_rn(x, y);
    h = *(uint32_t*)&hh;
    float rx = x - __bfloat162float(hh.x);
    float ry = y - __bfloat162float(hh.y);
    __nv_bfloat162 ll = __floats2bfloat162_rn(rx, ry);
    l = *(uint32_t*)&ll;
}

__device__ __forceinline__ void mma_bf16(float* c, uint32_t a0, uint32_t a1,
                                         uint32_t a2, uint32_t a3,
                                         uint32_t b0, uint32_t b1) {
    asm volatile(
        "mma.sync.aligned.m16n8k16.row.col.f32.bf16.bf16.f32 "
        "{%0,%1,%2,%3}, {%4,%5,%6,%7}, {%8,%9}, {%0,%1,%2,%3};"
        : "+f"(c[0]), "+f"(c[1]), "+f"(c[2]), "+f"(c[3])
        : "r"(a0), "r"(a1), "r"(a2), "r"(a3), "r"(b0), "r"(b1));
}

// ---------------- one-time weight split: [K][M] f32 -> [M][K/2] bf16x2 ------
__global__ void split_wb_k(const float* __restrict__ W1,
                           const float* __restrict__ W2,
                           const float* __restrict__ W3,
                           uint32_t* __restrict__ wbh,
                           uint32_t* __restrict__ wbl) {
    int i = blockIdx.x * blockDim.x + threadIdx.x;
    if (i >= WBTOT) return;
    const float* W; int K, M, idx;
    if (i < WB2)      { W = W1; K = IN_DIM; M = HID;  idx = i; }
    else if (i < WB3) { W = W2; K = HID;    M = HID;  idx = i - WB2; }
    else              { W = W3; K = HID;    M = OUTD; idx = i - WB3; }
    int kb2 = K / 2;
    int n = idx / kb2;
    int j = idx - n * kb2;
    float x = W[(size_t)(2 * j) * M + n];
    float y = W[(size_t)(2 * j + 1) * M + n];
    uint32_t h, l;
    split2_bf16(x, y, h, l);
    wbh[i] = h;
    wbl[i] = l;
}

// ---------------- GEMM + fused logit epilogue, 3xBF16 ----------------
// C[N,M] = A[N,K](lda) * B[K,M]; also as/ad += C . a_src/a_dst per head.
// BM=128, BN=128, BK=32, 256 threads = 8 warps (2m x 4n), warp tile 64x32.
#define PITCH 20
#define GEMM_SMEM (4 * 128 * PITCH * 4)
__global__ __launch_bounds__(256, 2)
void gemm_tc_k(const float* __restrict__ A, int lda,
               const uint32_t* __restrict__ Bhg,
               const uint32_t* __restrict__ Blg,
               float* __restrict__ C,
               int Nrows, int K, int M,
               const float* __restrict__ a_src,
               const float* __restrict__ a_dst,
               float* __restrict__ as_, float* __restrict__ ad_) {
    extern __shared__ uint32_t smem[];
    uint32_t (*Ah)[PITCH] = (uint32_t(*)[PITCH])smem;
    uint32_t (*Al)[PITCH] = (uint32_t(*)[PITCH])(smem + 128 * PITCH);
    uint32_t (*Bh)[PITCH] = (uint32_t(*)[PITCH])(smem + 2 * 128 * PITCH);
    uint32_t (*Bl)[PITCH] = (uint32_t(*)[PITCH])(smem + 3 * 128 * PITCH);

    const int tid = threadIdx.x;
    const int wid = tid >> 5;
    const int lane = tid & 31;
    const int gid = lane >> 2;
    const int t4 = lane & 3;
    const int rm = blockIdx.y * 128;
    const int cn = blockIdx.x * 128;
    const int wm = (wid & 1) * 64;
    const int wn = (wid >> 1) * 32;
    const int KB2 = K >> 1;

    float acc[4][4][4];
#pragma unroll
    for (int i = 0; i < 4; i++)
#pragma unroll
        for (int j = 0; j < 4; j++)
#pragma unroll
            for (int q = 0; q < 4; q++) acc[i][j][q] = 0.f;

    const int ar = tid >> 3;
    const int af = tid & 7;
    const int bn2 = tid >> 1;
    const int bq = (tid & 1) * 2;

    for (int k0 = 0; k0 < K; k0 += 32) {
#pragma unroll
        for (int l = 0; l < 4; l++) {
            int row = ar + 32 * l;
            int grow = rm + row;
            float4 v = make_float4(0.f, 0.f, 0.f, 0.f);
            if (grow < Nrows)
                v = *(const float4*)(A + (size_t)grow * lda + k0 + af * 4);
            uint32_t h0, l0, h1, l1;
            split2_bf16(v.x, v.y, h0, l0);
            split2_bf16(v.z, v.w, h1, l1);
            Ah[row][af * 2] = h0; Ah[row][af * 2 + 1] = h1;
            Al[row][af * 2] = l0; Al[row][af * 2 + 1] = l1;
        }
#pragma unroll
        for (int u = 0; u < 2; u++) {
            int q = bq + u;
            size_t go = (size_t)(cn + bn2) * KB2 + (k0 >> 1) + q * 4;
            *(uint4*)&Bh[bn2][q * 4] = *(const uint4*)(Bhg + go);
            *(uint4*)&Bl[bn2][q * 4] = *(const uint4*)(Blg + go);
        }
        __syncthreads();

#pragma unroll
        for (int s = 0; s < 2; s++) {
            const int jb = s * 8;
            uint32_t ah[4][4], al[4][4], bh[4][2], bl[4][2];
#pragma unroll
            for (int ma = 0; ma < 4; ma++) {
                int m = wm + ma * 16;
                ah[ma][0] = Ah[m + gid][jb + t4];
                ah[ma][1] = Ah[m + gid + 8][jb + t4];
                ah[ma][2] = Ah[m + gid][jb + t4 + 4];
                ah[ma][3] = Ah[m + gid + 8][jb + t4 + 4];
                al[ma][0] = Al[m + gid][jb + t4];
                al[ma][1] = Al[m + gid + 8][jb + t4];
                al[ma][2] = Al[m + gid][jb + t4 + 4];
                al[ma][3] = Al[m + gid + 8][jb + t4 + 4];
            }
#pragma unroll
            for (int nb = 0; nb < 4; nb++) {
                int col = wn + nb * 8 + gid;
                bh[nb][0] = Bh[col][jb + t4];
                bh[nb][1] = Bh[col][jb + t4 + 4];
                bl[nb][0] = Bl[col][jb + t4];
                bl[nb][1] = Bl[col][jb + t4 + 4];
            }
#pragma unroll
            for (int ma = 0; ma < 4; ma++)
#pragma unroll
                for (int nb = 0; nb < 4; nb++) {
                    float* c = acc[ma][nb];
                    mma_bf16(c, ah[ma][0], ah[ma][1], ah[ma][2], ah[ma][3],
                             bh[nb][0], bh[nb][1]);
                    mma_bf16(c, ah[ma][0], ah[ma][1], ah[ma][2], ah[ma][3],
                             bl[nb][0], bl[nb][1]);
                    mma_bf16(c, al[ma][0], al[ma][1], al[ma][2], al[ma][3],
                             bh[nb][0], bh[nb][1]);
                }
        }
        __syncthreads();
    }

    // ---- store C ----
#pragma unroll
    for (int ma = 0; ma < 4; ma++) {
        int r0 = rm + wm + ma * 16 + gid;
        int r1 = r0 + 8;
#pragma unroll
        for (int nb = 0; nb < 4; nb++) {
            int col = cn + wn + nb * 8 + 2 * t4;
            if (r0 < Nrows)
                *(float2*)(C + (size_t)r0 * M + col) =
                    make_float2(acc[ma][nb][0], acc[ma][nb][1]);
            if (r1 < Nrows)
                *(float2*)(C + (size_t)r1 * M + col) =
                    make_float2(acc[ma][nb][2], acc[ma][nb][3]);
        }
    }

    // ---- fused logit epilogue: warp's 32 cols lie in one head ----
    const int head = (cn + wn) / (M / 4);
    float av[4][2], dv[4][2];
#pragma unroll
    for (int nb = 0; nb < 4; nb++)
#pragma unroll
        for (int q = 0; q < 2; q++) {
            int col = cn + wn + nb * 8 + 2 * t4 + q;
            av[nb][q] = __ldg(a_src + col);
            dv[nb][q] = __ldg(a_dst + col);
        }
#pragma unroll
    for (int ma = 0; ma < 4; ma++) {
#pragma unroll
        for (int r = 0; r < 2; r++) {
            float vs = 0.f, vd = 0.f;
#pragma unroll
            for (int nb = 0; nb < 4; nb++)
#pragma unroll
                for (int q = 0; q < 2; q++) {
                    float c = acc[ma][nb][r * 2 + q];
                    vs += c * av[nb][q];
                    vd += c * dv[nb][q];
                }
            vs += __shfl_xor_sync(0xffffffffu, vs, 1);
            vs += __shfl_xor_sync(0xffffffffu, vs, 2);
            vd += __shfl_xor_sync(0xffffffffu, vd, 1);
            vd += __shfl_xor_sync(0xffffffffu, vd, 2);
            int row = rm + wm + ma * 16 + gid + r * 8;
            if (t4 == 0 && row < Nrows) {
                atomicAdd(&as_[row * 4 + head], vs);
                atomicAdd(&ad_[row * 4 + head], vd);
            }
        }
    }
}

// ---------------- fused softmax + gather aggregation (warp per node) -------
template<int M, int DORELU>
__global__ void gat_node_k(const int* __restrict__ roff,
                           const int* __restrict__ srcp,
                           const float* __restrict__ as_,
                           const float* __restrict__ ad_,
                           const float* __restrict__ hw,
                           float* __restrict__ wbuf,
                           const float* __restrict__ bias,
                           float* __restrict__ out, int ostride) {
    constexpr int NC = M / 32;
    int warp = (blockIdx.x * blockDim.x + threadIdx.x) >> 5;
    int lane = threadIdx.x & 31;
    if (warp >= NN) return;
    const int n = warp;
    const int beg = roff[n], end = roff[n + 1];
    const int h = lane & 3, slot = lane >> 2;

    float adv = ad_[n * 4 + h];
    float mx = -CUDART_INF_F;
    for (int i = beg + slot; i < end; i += 8) {
        int s = srcp[i];
        float v = as_[s * 4 + h] + adv;
        v = (v > 0.f) ? v : NEG * v;
        wbuf[(size_t)i * 4 + h] = v;
        mx = fmaxf(mx, v);
    }
    mx = fmaxf(mx, __shfl_xor_sync(0xffffffffu, mx, 4));
    mx = fmaxf(mx, __shfl_xor_sync(0xffffffffu, mx, 8));
    mx = fmaxf(mx, __shfl_xor_sync(0xffffffffu, mx, 16));

    float den = 0.f;
    for (int i = beg + slot; i < end; i += 8) {
        float w = expf(wbuf[(size_t)i * 4 + h] - mx);
        wbuf[(size_t)i * 4 + h] = w;
        den += w;
    }
    den += __shfl_xor_sync(0xffffffffu, den, 4);
    den += __shfl_xor_sync(0xffffffffu, den, 8);
    den += __shfl_xor_sync(0xffffffffu, den, 16);
    den += 1e-16f;
    __threadfence_block();
    __syncwarp();

    const int hh = lane >> 3;
    float dinv = 1.0f / __shfl_sync(0xffffffffu, den, hh);
    float acc[NC];
#pragma unroll
    for (int j = 0; j < NC; j++) acc[j] = 0.f;
    const int colbase = lane * NC;
    for (int i = beg; i < end; i++) {
        int s = srcp[i];
        float4 w4 = *(const float4*)(wbuf + (size_t)i * 4);
        float wv = (hh == 0) ? w4.x : (hh == 1) ? w4.y : (hh == 2) ? w4.z : w4.w;
        float a = wv * dinv;
        const float* hp = hw + (size_t)s * M + colbase;
#pragma unroll
        for (int j = 0; j < NC; j += 4) {
            float4 v = *(const float4*)(hp + j);
            acc[j + 0] += a * v.x;
            acc[j + 1] += a * v.y;
            acc[j + 2] += a * v.z;
            acc[j + 3] += a * v.w;
        }
    }
    float* op = out + (size_t)n * ostride + colbase;
    const float* bp = bias + colbase;
#pragma unroll
    for (int j = 0; j < NC; j++) {
        float v = acc[j] + bp[j];
        if (DORELU) v = fmaxf(v, 0.f);
        op[j] = v;
    }
}

// ---------------- host orchestration ----------------
extern "C" void kernel_launch(void* const* d_in, const int* in_sizes, int n_in,
                              void* d_out, int out_size) {
    const float* x  = (const float*)d_in[0];
    const void*  ei = d_in[1];
    const float* asrc[3] = {(const float*)d_in[3], (const float*)d_in[7],
                            (const float*)d_in[11]};
    const float* adst[3] = {(const float*)d_in[4], (const float*)d_in[8],
                            (const float*)d_in[12]};
    const float* bias[3] = {(const float*)d_in[5], (const float*)d_in[9],
                            (const float*)d_in[13]};
    float* out = (float*)d_out;

    static cudaStream_t ss[NCHAIN - 1];
    static cudaEvent_t ev_fork, ev_join[NCHAIN - 1];
    static bool inited = false;
    if (!inited) {
        inited = true;
        for (int i = 0; i < NCHAIN - 1; i++) {
            cudaStreamCreateWithFlags(&ss[i], cudaStreamNonBlocking);
            cudaEventCreateWithFlags(&ev_join[i], cudaEventDisableTiming);
        }
        cudaEventCreateWithFlags(&ev_fork, cudaEventDisableTiming);
        cudaFuncSetAttribute(gemm_tc_k,
                             cudaFuncAttributeMaxDynamicSharedMemorySize,
                             GEMM_SMEM);
    }

    float *p_hw[NCHAIN], *p_x[NCHAIN], *p_w[NCHAIN], *p_asd[NCHAIN];
    {
        float4 *b_hw, *b_x, *b_w; float *b_asd;
        cudaGetSymbolAddress((void**)&b_hw, g_hw4);
        cudaGetSymbolAddress((void**)&b_x, g_x4);
        cudaGetSymbolAddress((void**)&b_w, g_w4);
        cudaGetSymbolAddress((void**)&b_asd, g_asd);
        for (int c = 0; c < NCHAIN; c++) {
            p_hw[c]  = (float*)(b_hw + (size_t)c * (NN * HID / 4));
            p_x[c]   = (float*)(b_x  + (size_t)c * (NN * HID / 4));
            p_w[c]   = (float*)(b_w  + (size_t)c * EE);
            p_asd[c] = b_asd + (size_t)c * (2 * NN * HEADS);
        }
    }
    uint32_t *p_wbh, *p_wbl;
    cudaGetSymbolAddress((void**)&p_wbh, g_wbh);
    cudaGetSymbolAddress((void**)&p_wbl, g_wbl);
    int *p_src, *p_dst, *p_cnt, *p_roff, *p_cur, *p_srcp;
    cudaGetSymbolAddress((void**)&p_src, g_src);
    cudaGetSymbolAddress((void**)&p_dst, g_dst);
    cudaGetSymbolAddress((void**)&p_cnt, g_cnt);
    cudaGetSymbolAddress((void**)&p_roff, g_roff);
    cudaGetSymbolAddress((void**)&p_cur, g_cur);
    cudaGetSymbolAddress((void**)&p_srcp, g_srcp);

    const uint32_t* wbh[3] = {p_wbh + WB1, p_wbh + WB2, p_wbh + WB3};
    const uint32_t* wbl[3] = {p_wbl + WB1, p_wbl + WB2, p_wbl + WB3};

    // --- preprocessing on stream 0 ---
    detconv_k<<<(EE + 255) / 256, 256>>>(ei);
    hist_k<<<(EE + 255) / 256, 256>>>(p_dst, p_cnt);
    scan_k<<<1, 1024>>>(p_cnt, p_roff, p_cur);
    scatter_k<<<(EE + 255) / 256, 256>>>(p_src, p_dst, p_cur, p_srcp);
    split_wb_k<<<(WBTOT + 255) / 256, 256>>>((const float*)d_in[2],
                                             (const float*)d_in[6],
                                             (const float*)d_in[10],
                                             p_wbh, p_wbl);

    cudaEventRecord(ev_fork, 0);
    for (int i = 0; i < NCHAIN - 1; i++)
        cudaStreamWaitEvent(ss[i], ev_fork, 0);

    const int npblk = (NN * 32 + 255) / 256;
    const int rowblk = (NN + 127) / 128;

    for (int c = 0; c < NCHAIN; c++) {
        cudaStream_t st = (c == 0) ? (cudaStream_t)0 : ss[c - 1];
        float* as_ = p_asd[c];
        float* ad_ = p_asd[c] + NN * HEADS;
        for (int t = c; t < TT; t += NCHAIN) {
            // layer 1
            {
                cudaMemsetAsync(p_asd[c], 0, 2 * NN * HEADS * sizeof(float), st);
                dim3 gg(HID / 128, rowblk);
                gemm_tc_k<<<gg, 256, GEMM_SMEM, st>>>(
                    x + (size_t)t * IN_DIM, TT * IN_DIM, wbh[0], wbl[0],
                    p_hw[c], NN, IN_DIM, HID, asrc[0], adst[0], as_, ad_);
                gat_node_k<HID, 1><<<npblk, 256, 0, st>>>(
                    p_roff, p_srcp, as_, ad_, p_hw[c], p_w[c],
                    bias[0], p_x[c], HID);
            }
            // layer 2
            {
                cudaMemsetAsync(p_asd[c], 0, 2 * NN * HEADS * sizeof(float), st);
                dim3 gg(HID / 128, rowblk);
                gemm_tc_k<<<gg, 256, GEMM_SMEM, st>>>(
                    p_x[c], HID, wbh[1], wbl[1], p_hw[c], NN, HID, HID,
                    asrc[1], adst[1], as_, ad_);
                gat_node_k<HID, 1><<<npblk, 256, 0, st>>>(
                    p_roff, p_srcp, as_, ad_, p_hw[c], p_w[c],
                    bias[1], p_x[c], HID);
            }
            // layer 3
            {
                cudaMemsetAsync(p_asd[c], 0, 2 * NN * HEADS * sizeof(float), st);
                dim3 gg(OUTD / 128, rowblk);
                gemm_tc_k<<<gg, 256, GEMM_SMEM, st>>>(
                    p_x[c], HID, wbh[2], wbl[2], p_hw[c], NN, HID, OUTD,
                    asrc[2], adst[2], as_, ad_);
                gat_node_k<OUTD, 0><<<npblk, 256, 0, st>>>(
                    p_roff, p_srcp, as_, ad_, p_hw[c], p_w[c],
                    bias[2], out + (size_t)t * OUTD, TT * OUTD);
            }
        }
    }

    for (int i = 0; i < NCHAIN - 1; i++) {
        cudaEventRecord(ev_join[i], ss[i]);
        cudaStreamWaitEvent((cudaStream_t)0, ev_join[i], 0);
    }
}

// round 13
// speedup vs baseline: 1.4664x; 1.1324x over previous
#include <cuda_runtime.h>
#include <cuda_bf16.h>
#include <cuda_fp16.h>
#include <math_constants.h>
#include <cstdint>

// ---------------- problem constants ----------------
#define NN      20000
#define EE      320000
#define TT      12
#define IN_DIM  128
#define HID     256
#define OUTD    128
#define HEADS   4
#define NEG     0.2f
#define NCHAIN  4            // 3 extra streams max (R11: more trips alloc guard)

// packed bf16 weight tables, layout [M][K/2] u32
#define WB1 0
#define WB2 16384
#define WB3 49152
#define WBTOT 65536

// ---------------- device scratch (per-chain) ----------------
__device__ float4   g_hw4[NCHAIN][(size_t)NN * HID / 4];   // fp32 or fp16 h
__device__ float4   g_x4 [NCHAIN][(size_t)NN * HID / 4];
__device__ float4   g_w4 [NCHAIN][EE];
__device__ float    g_asd[NCHAIN][2 * NN * HEADS];
__device__ uint32_t g_wbh[WBTOT];
__device__ uint32_t g_wbl[WBTOT];
__device__ int      g_src [EE];
__device__ int      g_dst [EE];
__device__ int      g_cnt [NN];
__device__ int      g_roff[NN + 1];
__device__ int      g_cur [NN];
__device__ int      g_srcp[EE];

// ---------------- edge-index dtype detect + normalize (+ cnt zero) ---------
__global__ void detconv_k(const void* ei) {
    __shared__ int is64;
    if (threadIdx.x == 0) {
        int bad = 0;
        const long long* p = (const long long*)ei;
        for (int i = 0; i < 256; i++) {
            long long v = p[i];
            if (v < 0 || v >= NN) { bad = 1; break; }
        }
        is64 = bad ? 0 : 1;
    }
    __syncthreads();
    int i = blockIdx.x * blockDim.x + threadIdx.x;
    if (i < NN) g_cnt[i] = 0;
    if (i >= EE) return;
    if (is64) {
        const long long* p = (const long long*)ei;
        g_src[i] = (int)p[i];
        g_dst[i] = (int)p[EE + i];
    } else {
        const int* p = (const int*)ei;
        g_src[i] = p[i];
        g_dst[i] = p[EE + i];
    }
}

// ---------------- CSR build (by dst) ----------------
__global__ void hist_k(const int* __restrict__ dst, int* __restrict__ cnt) {
    int e = blockIdx.x * blockDim.x + threadIdx.x;
    if (e < EE) atomicAdd(&cnt[dst[e]], 1);
}

__global__ void scan_k(const int* __restrict__ cnt, int* __restrict__ roff,
                       int* __restrict__ cur) {
    __shared__ int part[1024];
    const int chunk = (NN + 1023) / 1024;
    int t = threadIdx.x;
    int lo = t * chunk;
    int hi = lo + chunk; if (hi > NN) hi = NN;
    int s = 0;
    for (int i = lo; i < hi; i++) s += cnt[i];
    part[t] = s;
    __syncthreads();
    for (int o = 1; o < 1024; o <<= 1) {
        int v = (t >= o) ? part[t - o] : 0;
        __syncthreads();
        part[t] += v;
        __syncthreads();
    }
    int base = (t == 0) ? 0 : part[t - 1];
    for (int i = lo; i < hi; i++) {
        roff[i] = base;
        cur[i] = base;
        base += cnt[i];
    }
    if (t == 1023) roff[NN] = base;
}

__global__ void scatter_k(const int* __restrict__ src,
                          const int* __restrict__ dst,
                          int* __restrict__ cur, int* __restrict__ srcp) {
    int e = blockIdx.x * blockDim.x + threadIdx.x;
    if (e >= EE) return;
    int p = atomicAdd(&cur[dst[e]], 1);
    srcp[p] = src[e];
}

// ---------------- bf16 helpers ----------------
__device__ __forceinline__ void split2_bf16(float x, float y,
                                            uint32_t& h, uint32_t& l) {
    __nv_bfloat162 hh = __floats2bfloat162_rn(x, y);
    h = *(uint32_t*)&hh;
    float rx = x - __bfloat162float(hh.x);
    float ry = y - __bfloat162float(hh.y);
    __nv_bfloat162 ll = __floats2bfloat162_rn(rx, ry);
    l = *(uint32_t*)&ll;
}

__device__ __forceinline__ void mma_bf16(float* c, uint32_t a0, uint32_t a1,
                                         uint32_t a2, uint32_t a3,
                                         uint32_t b0, uint32_t b1) {
    asm volatile(
        "mma.sync.aligned.m16n8k16.row.col.f32.bf16.bf16.f32 "
        "{%0,%1,%2,%3}, {%4,%5,%6,%7}, {%8,%9}, {%0,%1,%2,%3};"
        : "+f"(c[0]), "+f"(c[1]), "+f"(c[2]), "+f"(c[3])
        : "r"(a0), "r"(a1), "r"(a2), "r"(a3), "r"(b0), "r"(b1));
}

// ---------------- one-time weight split: [K][M] f32 -> [M][K/2] bf16x2 ------
__global__ void split_wb_k(const float* __restrict__ W1,
                           const float* __restrict__ W2,
                           const float* __restrict__ W3,
                           uint32_t* __restrict__ wbh,
                           uint32_t* __restrict__ wbl) {
    int i = blockIdx.x * blockDim.x + threadIdx.x;
    if (i >= WBTOT) return;
    const float* W; int K, M, idx;
    if (i < WB2)      { W = W1; K = IN_DIM; M = HID;  idx = i; }
    else if (i < WB3) { W = W2; K = HID;    M = HID;  idx = i - WB2; }
    else              { W = W3; K = HID;    M = OUTD; idx = i - WB3; }
    int kb2 = K / 2;
    int n = idx / kb2;
    int j = idx - n * kb2;
    float x = W[(size_t)(2 * j) * M + n];
    float y = W[(size_t)(2 * j + 1) * M + n];
    uint32_t h, l;
    split2_bf16(x, y, h, l);
    wbh[i] = h;
    wbl[i] = l;
}

// ---------------- GEMM + fused logit epilogue, 3xBF16 ----------------
// C[N,M] = A[N,K](lda) * B[K,M]; also as/ad += C . a_src/a_dst per head.
// OUTHALF: store C as fp16 (consumed only by the gather).
#define PITCH 20
#define GEMM_SMEM (4 * 128 * PITCH * 4)
template<int OUTHALF>
__global__ __launch_bounds__(256, 2)
void gemm_tc_k(const float* __restrict__ A, int lda,
               const uint32_t* __restrict__ Bhg,
               const uint32_t* __restrict__ Blg,
               void* __restrict__ Cv,
               int Nrows, int K, int M,
               const float* __restrict__ a_src,
               const float* __restrict__ a_dst,
               float* __restrict__ as_, float* __restrict__ ad_) {
    extern __shared__ uint32_t smem[];
    uint32_t (*Ah)[PITCH] = (uint32_t(*)[PITCH])smem;
    uint32_t (*Al)[PITCH] = (uint32_t(*)[PITCH])(smem + 128 * PITCH);
    uint32_t (*Bh)[PITCH] = (uint32_t(*)[PITCH])(smem + 2 * 128 * PITCH);
    uint32_t (*Bl)[PITCH] = (uint32_t(*)[PITCH])(smem + 3 * 128 * PITCH);

    const int tid = threadIdx.x;
    const int wid = tid >> 5;
    const int lane = tid & 31;
    const int gid = lane >> 2;
    const int t4 = lane & 3;
    const int rm = blockIdx.y * 128;
    const int cn = blockIdx.x * 128;
    const int wm = (wid & 1) * 64;
    const int wn = (wid >> 1) * 32;
    const int KB2 = K >> 1;

    float acc[4][4][4];
#pragma unroll
    for (int i = 0; i < 4; i++)
#pragma unroll
        for (int j = 0; j < 4; j++)
#pragma unroll
            for (int q = 0; q < 4; q++) acc[i][j][q] = 0.f;

    const int ar = tid >> 3;
    const int af = tid & 7;
    const int bn2 = tid >> 1;
    const int bq = (tid & 1) * 2;

    for (int k0 = 0; k0 < K; k0 += 32) {
#pragma unroll
        for (int l = 0; l < 4; l++) {
            int row = ar + 32 * l;
            int grow = rm + row;
            float4 v = make_float4(0.f, 0.f, 0.f, 0.f);
            if (grow < Nrows)
                v = *(const float4*)(A + (size_t)grow * lda + k0 + af * 4);
            uint32_t h0, l0, h1, l1;
            split2_bf16(v.x, v.y, h0, l0);
            split2_bf16(v.z, v.w, h1, l1);
            Ah[row][af * 2] = h0; Ah[row][af * 2 + 1] = h1;
            Al[row][af * 2] = l0; Al[row][af * 2 + 1] = l1;
        }
#pragma unroll
        for (int u = 0; u < 2; u++) {
            int q = bq + u;
            size_t go = (size_t)(cn + bn2) * KB2 + (k0 >> 1) + q * 4;
            *(uint4*)&Bh[bn2][q * 4] = *(const uint4*)(Bhg + go);
            *(uint4*)&Bl[bn2][q * 4] = *(const uint4*)(Blg + go);
        }
        __syncthreads();

#pragma unroll
        for (int s = 0; s < 2; s++) {
            const int jb = s * 8;
            uint32_t ah[4][4], al[4][4], bh[4][2], bl[4][2];
#pragma unroll
            for (int ma = 0; ma < 4; ma++) {
                int m = wm + ma * 16;
                ah[ma][0] = Ah[m + gid][jb + t4];
                ah[ma][1] = Ah[m + gid + 8][jb + t4];
                ah[ma][2] = Ah[m + gid][jb + t4 + 4];
                ah[ma][3] = Ah[m + gid + 8][jb + t4 + 4];
                al[ma][0] = Al[m + gid][jb + t4];
                al[ma][1] = Al[m + gid + 8][jb + t4];
                al[ma][2] = Al[m + gid][jb + t4 + 4];
                al[ma][3] = Al[m + gid + 8][jb + t4 + 4];
            }
#pragma unroll
            for (int nb = 0; nb < 4; nb++) {
                int col = wn + nb * 8 + gid;
                bh[nb][0] = Bh[col][jb + t4];
                bh[nb][1] = Bh[col][jb + t4 + 4];
                bl[nb][0] = Bl[col][jb + t4];
                bl[nb][1] = Bl[col][jb + t4 + 4];
            }
#pragma unroll
            for (int ma = 0; ma < 4; ma++)
#pragma unroll
                for (int nb = 0; nb < 4; nb++) {
                    float* c = acc[ma][nb];
                    mma_bf16(c, ah[ma][0], ah[ma][1], ah[ma][2], ah[ma][3],
                             bh[nb][0], bh[nb][1]);
                    mma_bf16(c, ah[ma][0], ah[ma][1], ah[ma][2], ah[ma][3],
                             bl[nb][0], bl[nb][1]);
                    mma_bf16(c, al[ma][0], al[ma][1], al[ma][2], al[ma][3],
                             bh[nb][0], bh[nb][1]);
                }
        }
        __syncthreads();
    }

    // ---- store C (fp32 or fp16) ----
#pragma unroll
    for (int ma = 0; ma < 4; ma++) {
        int r0 = rm + wm + ma * 16 + gid;
        int r1 = r0 + 8;
#pragma unroll
        for (int nb = 0; nb < 4; nb++) {
            int col = cn + wn + nb * 8 + 2 * t4;
            if (OUTHALF) {
                __half* Ch = (__half*)Cv;
                if (r0 < Nrows)
                    *(__half2*)(Ch + (size_t)r0 * M + col) =
                        __floats2half2_rn(acc[ma][nb][0], acc[ma][nb][1]);
                if (r1 < Nrows)
                    *(__half2*)(Ch + (size_t)r1 * M + col) =
                        __floats2half2_rn(acc[ma][nb][2], acc[ma][nb][3]);
            } else {
                float* C = (float*)Cv;
                if (r0 < Nrows)
                    *(float2*)(C + (size_t)r0 * M + col) =
                        make_float2(acc[ma][nb][0], acc[ma][nb][1]);
                if (r1 < Nrows)
                    *(float2*)(C + (size_t)r1 * M + col) =
                        make_float2(acc[ma][nb][2], acc[ma][nb][3]);
            }
        }
    }

    // ---- fused logit epilogue (fp32 accumulators -> exact logits) ----
    const int head = (cn + wn) / (M / 4);
    float av[4][2], dv[4][2];
#pragma unroll
    for (int nb = 0; nb < 4; nb++)
#pragma unroll
        for (int q = 0; q < 2; q++) {
            int col = cn + wn + nb * 8 + 2 * t4 + q;
            av[nb][q] = __ldg(a_src + col);
            dv[nb][q] = __ldg(a_dst + col);
        }
#pragma unroll
    for (int ma = 0; ma < 4; ma++) {
#pragma unroll
        for (int r = 0; r < 2; r++) {
            float vs = 0.f, vd = 0.f;
#pragma unroll
            for (int nb = 0; nb < 4; nb++)
#pragma unroll
                for (int q = 0; q < 2; q++) {
                    float c = acc[ma][nb][r * 2 + q];
                    vs += c * av[nb][q];
                    vd += c * dv[nb][q];
                }
            vs += __shfl_xor_sync(0xffffffffu, vs, 1);
            vs += __shfl_xor_sync(0xffffffffu, vs, 2);
            vd += __shfl_xor_sync(0xffffffffu, vd, 1);
            vd += __shfl_xor_sync(0xffffffffu, vd, 2);
            int row = rm + wm + ma * 16 + gid + r * 8;
            if (t4 == 0 && row < Nrows) {
                atomicAdd(&as_[row * 4 + head], vs);
                atomicAdd(&ad_[row * 4 + head], vd);
            }
        }
    }
}

// ---------------- fused softmax + gather aggregation (warp per node) -------
// HALFH: h table stored as fp16
template<int M, int DORELU, int HALFH>
__global__ void gat_node_k(const int* __restrict__ roff,
                           const int* __restrict__ srcp,
                           const float* __restrict__ as_,
                           const float* __restrict__ ad_,
                           const void* __restrict__ hw,
                           float* __restrict__ wbuf,
                           const float* __restrict__ bias,
                           float* __restrict__ out, int ostride) {
    constexpr int NC = M / 32;
    int warp = (blockIdx.x * blockDim.x + threadIdx.x) >> 5;
    int lane = threadIdx.x & 31;
    if (warp >= NN) return;
    const int n = warp;
    const int beg = roff[n], end = roff[n + 1];
    const int h = lane & 3, slot = lane >> 2;

    float adv = ad_[n * 4 + h];
    float mx = -CUDART_INF_F;
    for (int i = beg + slot; i < end; i += 8) {
        int s = srcp[i];
        float v = as_[s * 4 + h] + adv;
        v = (v > 0.f) ? v : NEG * v;
        wbuf[(size_t)i * 4 + h] = v;
        mx = fmaxf(mx, v);
    }
    mx = fmaxf(mx, __shfl_xor_sync(0xffffffffu, mx, 4));
    mx = fmaxf(mx, __shfl_xor_sync(0xffffffffu, mx, 8));
    mx = fmaxf(mx, __shfl_xor_sync(0xffffffffu, mx, 16));

    float den = 0.f;
    for (int i = beg + slot; i < end; i += 8) {
        float w = expf(wbuf[(size_t)i * 4 + h] - mx);
        wbuf[(size_t)i * 4 + h] = w;
        den += w;
    }
    den += __shfl_xor_sync(0xffffffffu, den, 4);
    den += __shfl_xor_sync(0xffffffffu, den, 8);
    den += __shfl_xor_sync(0xffffffffu, den, 16);
    den += 1e-16f;
    __threadfence_block();
    __syncwarp();

    const int hh = lane >> 3;
    float dinv = 1.0f / __shfl_sync(0xffffffffu, den, hh);
    float acc[NC];
#pragma unroll
    for (int j = 0; j < NC; j++) acc[j] = 0.f;
    const int colbase = lane * NC;
    for (int i = beg; i < end; i++) {
        int s = srcp[i];
        float4 w4 = *(const float4*)(wbuf + (size_t)i * 4);
        float wv = (hh == 0) ? w4.x : (hh == 1) ? w4.y : (hh == 2) ? w4.z : w4.w;
        float a = wv * dinv;
        if (HALFH) {
            const __half* hp = (const __half*)hw + (size_t)s * M + colbase;
            uint4 u = *(const uint4*)hp;   // NC=8 halves = 16B
            float2 f0 = __half22float2(*(const __half2*)&u.x);
            float2 f1 = __half22float2(*(const __half2*)&u.y);
            float2 f2 = __half22float2(*(const __half2*)&u.z);
            float2 f3 = __half22float2(*(const __half2*)&u.w);
            acc[0] += a * f0.x; acc[1] += a * f0.y;
            acc[2] += a * f1.x; acc[3] += a * f1.y;
            acc[4] += a * f2.x; acc[5] += a * f2.y;
            acc[6] += a * f3.x; acc[7] += a * f3.y;
        } else {
            const float* hp = (const float*)hw + (size_t)s * M + colbase;
#pragma unroll
            for (int j = 0; j < NC; j += 4) {
                float4 v = *(const float4*)(hp + j);
                acc[j + 0] += a * v.x;
                acc[j + 1] += a * v.y;
                acc[j + 2] += a * v.z;
                acc[j + 3] += a * v.w;
            }
        }
    }
    float* op = out + (size_t)n * ostride + colbase;
    const float* bp = bias + colbase;
#pragma unroll
    for (int j = 0; j < NC; j++) {
        float v = acc[j] + bp[j];
        if (DORELU) v = fmaxf(v, 0.f);
        op[j] = v;
    }
}

// ---------------- host orchestration ----------------
extern "C" void kernel_launch(void* const* d_in, const int* in_sizes, int n_in,
                              void* d_out, int out_size) {
    const float* x  = (const float*)d_in[0];
    const void*  ei = d_in[1];
    const float* asrc[3] = {(const float*)d_in[3], (const float*)d_in[7],
                            (const float*)d_in[11]};
    const float* adst[3] = {(const float*)d_in[4], (const float*)d_in[8],
                            (const float*)d_in[12]};
    const float* bias[3] = {(const float*)d_in[5], (const float*)d_in[9],
                            (const float*)d_in[13]};
    float* out = (float*)d_out;

    static cudaStream_t ss[NCHAIN - 1];
    static cudaEvent_t ev_fork, ev_join[NCHAIN - 1];
    static bool inited = false;
    if (!inited) {
        inited = true;
        for (int i = 0; i < NCHAIN - 1; i++) {
            cudaStreamCreateWithFlags(&ss[i], cudaStreamNonBlocking);
            cudaEventCreateWithFlags(&ev_join[i], cudaEventDisableTiming);
        }
        cudaEventCreateWithFlags(&ev_fork, cudaEventDisableTiming);
        cudaFuncSetAttribute(gemm_tc_k<0>,
                             cudaFuncAttributeMaxDynamicSharedMemorySize,
                             GEMM_SMEM);
        cudaFuncSetAttribute(gemm_tc_k<1>,
                             cudaFuncAttributeMaxDynamicSharedMemorySize,
                             GEMM_SMEM);
    }

    void *p_hw[NCHAIN];
    float *p_x[NCHAIN], *p_w[NCHAIN], *p_asd[NCHAIN];
    {
        float4 *b_hw, *b_x, *b_w; float *b_asd;
        cudaGetSymbolAddress((void**)&b_hw, g_hw4);
        cudaGetSymbolAddress((void**)&b_x, g_x4);
        cudaGetSymbolAddress((void**)&b_w, g_w4);
        cudaGetSymbolAddress((void**)&b_asd, g_asd);
        for (int c = 0; c < NCHAIN; c++) {
            p_hw[c]  = (void*)(b_hw + (size_t)c * (NN * HID / 4));
            p_x[c]   = (float*)(b_x  + (size_t)c * (NN * HID / 4));
            p_w[c]   = (float*)(b_w  + (size_t)c * EE);
            p_asd[c] = b_asd + (size_t)c * (2 * NN * HEADS);
        }
    }
    uint32_t *p_wbh, *p_wbl;
    cudaGetSymbolAddress((void**)&p_wbh, g_wbh);
    cudaGetSymbolAddress((void**)&p_wbl, g_wbl);
    int *p_src, *p_dst, *p_cnt, *p_roff, *p_cur, *p_srcp;
    cudaGetSymbolAddress((void**)&p_src, g_src);
    cudaGetSymbolAddress((void**)&p_dst, g_dst);
    cudaGetSymbolAddress((void**)&p_cnt, g_cnt);
    cudaGetSymbolAddress((void**)&p_roff, g_roff);
    cudaGetSymbolAddress((void**)&p_cur, g_cur);
    cudaGetSymbolAddress((void**)&p_srcp, g_srcp);

    const uint32_t* wbh[3] = {p_wbh + WB1, p_wbh + WB2, p_wbh + WB3};
    const uint32_t* wbl[3] = {p_wbl + WB1, p_wbl + WB2, p_wbl + WB3};

    // --- preprocessing on stream 0 ---
    detconv_k<<<(EE + 255) / 256, 256>>>(ei);
    hist_k<<<(EE + 255) / 256, 256>>>(p_dst, p_cnt);
    scan_k<<<1, 1024>>>(p_cnt, p_roff, p_cur);
    scatter_k<<<(EE + 255) / 256, 256>>>(p_src, p_dst, p_cur, p_srcp);
    split_wb_k<<<(WBTOT + 255) / 256, 256>>>((const float*)d_in[2],
                                             (const float*)d_in[6],
                                             (const float*)d_in[10],
                                             p_wbh, p_wbl);

    cudaEventRecord(ev_fork, 0);
    for (int i = 0; i < NCHAIN - 1; i++)
        cudaStreamWaitEvent(ss[i], ev_fork, 0);

    const int npblk = (NN * 32 + 255) / 256;
    const int rowblk = (NN + 127) / 128;

    for (int c = 0; c < NCHAIN; c++) {
        cudaStream_t st = (c == 0) ? (cudaStream_t)0 : ss[c - 1];
        float* as_ = p_asd[c];
        float* ad_ = p_asd[c] + NN * HEADS;
        for (int t = c; t < TT; t += NCHAIN) {
            // layer 1 (fp16 h)
            {
                cudaMemsetAsync(p_asd[c], 0, 2 * NN * HEADS * sizeof(float), st);
                dim3 gg(HID / 128, rowblk);
                gemm_tc_k<1><<<gg, 256, GEMM_SMEM, st>>>(
                    x + (size_t)t * IN_DIM, TT * IN_DIM, wbh[0], wbl[0],
                    p_hw[c], NN, IN_DIM, HID, asrc[0], adst[0], as_, ad_);
                gat_node_k<HID, 1, 1><<<npblk, 256, 0, st>>>(
                    p_roff, p_srcp, as_, ad_, p_hw[c], p_w[c],
                    bias[0], p_x[c], HID);
            }
            // layer 2 (fp16 h)
            {
                cudaMemsetAsync(p_asd[c], 0, 2 * NN * HEADS * sizeof(float), st);
                dim3 gg(HID / 128, rowblk);
                gemm_tc_k<1><<<gg, 256, GEMM_SMEM, st>>>(
                    p_x[c], HID, wbh[1], wbl[1], p_hw[c], NN, HID, HID,
                    asrc[1], adst[1], as_, ad_);
                gat_node_k<HID, 1, 1><<<npblk, 256, 0, st>>>(
                    p_roff, p_srcp, as_, ad_, p_hw[c], p_w[c],
                    bias[1], p_x[c], HID);
            }
            // layer 3 (fp32 h — precision hedge)
            {
                cudaMemsetAsync(p_asd[c], 0, 2 * NN * HEADS * sizeof(float), st);
                dim3 gg(OUTD / 128, rowblk);
                gemm_tc_k<0><<<gg, 256, GEMM_SMEM, st>>>(
                    p_x[c], HID, wbh[2], wbl[2], p_hw[c], NN, HID, OUTD,
                    asrc[2], adst[2], as_, ad_);
                gat_node_k<OUTD, 0, 0><<<npblk, 256, 0, st>>>(
                    p_roff, p_srcp, as_, ad_, p_hw[c], p_w[c],
                    bias[2], out + (size_t)t * OUTD, TT * OUTD);
            }
        }
    }

    for (int i = 0; i < NCHAIN - 1; i++) {
        cudaEventRecord(ev_join[i], ss[i]);
        cudaStreamWaitEvent((cudaStream_t)0, ev_join[i], 0);
    }
}

// round 14
// speedup vs baseline: 1.5997x; 1.0909x over previous
#include <cuda_runtime.h>
#include <cuda_bf16.h>
#include <cuda_fp16.h>
#include <math_constants.h>
#include <cstdint>

// ---------------- problem constants ----------------
#define NN      20000
#define EE      320000
#define TT      12
#define IN_DIM  128
#define HID     256
#define OUTD    128
#define HEADS   4
#define NEG     0.2f
#define NCHAIN  4            // 3 extra streams max (R11: more trips alloc guard)

// packed bf16 weight tables, layout [M][K/2] u32
#define WB1 0
#define WB2 16384
#define WB3 49152
#define WBTOT 65536

// ---------------- device scratch (per-chain) ----------------
__device__ float4   g_hw4[NCHAIN][(size_t)NN * HID / 4];   // h (fp16 now)
__device__ float4   g_x4 [NCHAIN][(size_t)NN * HID / 4];   // x (fp16 now)
__device__ float4   g_w4 [NCHAIN][EE];
__device__ float    g_asd[NCHAIN][2 * NN * HEADS];
__device__ uint32_t g_wbh[WBTOT];
__device__ uint32_t g_wbl[WBTOT];
__device__ int      g_src [EE];
__device__ int      g_dst [EE];
__device__ int      g_cnt [NN];
__device__ int      g_roff[NN + 1];
__device__ int      g_cur [NN];
__device__ int      g_srcp[EE];

// ---------------- edge-index dtype detect + normalize (+ cnt zero) ---------
__global__ void detconv_k(const void* ei) {
    __shared__ int is64;
    if (threadIdx.x == 0) {
        int bad = 0;
        const long long* p = (const long long*)ei;
        for (int i = 0; i < 256; i++) {
            long long v = p[i];
            if (v < 0 || v >= NN) { bad = 1; break; }
        }
        is64 = bad ? 0 : 1;
    }
    __syncthreads();
    int i = blockIdx.x * blockDim.x + threadIdx.x;
    if (i < NN) g_cnt[i] = 0;
    if (i >= EE) return;
    if (is64) {
        const long long* p = (const long long*)ei;
        g_src[i] = (int)p[i];
        g_dst[i] = (int)p[EE + i];
    } else {
        const int* p = (const int*)ei;
        g_src[i] = p[i];
        g_dst[i] = p[EE + i];
    }
}

// ---------------- CSR build (by dst) ----------------
__global__ void hist_k(const int* __restrict__ dst, int* __restrict__ cnt) {
    int e = blockIdx.x * blockDim.x + threadIdx.x;
    if (e < EE) atomicAdd(&cnt[dst[e]], 1);
}

__global__ void scan_k(const int* __restrict__ cnt, int* __restrict__ roff,
                       int* __restrict__ cur) {
    __shared__ int part[1024];
    const int chunk = (NN + 1023) / 1024;
    int t = threadIdx.x;
    int lo = t * chunk;
    int hi = lo + chunk; if (hi > NN) hi = NN;
    int s = 0;
    for (int i = lo; i < hi; i++) s += cnt[i];
    part[t] = s;
    __syncthreads();
    for (int o = 1; o < 1024; o <<= 1) {
        int v = (t >= o) ? part[t - o] : 0;
        __syncthreads();
        part[t] += v;
        __syncthreads();
    }
    int base = (t == 0) ? 0 : part[t - 1];
    for (int i = lo; i < hi; i++) {
        roff[i] = base;
        cur[i] = base;
        base += cnt[i];
    }
    if (t == 1023) roff[NN] = base;
}

__global__ void scatter_k(const int* __restrict__ src,
                          const int* __restrict__ dst,
                          int* __restrict__ cur, int* __restrict__ srcp) {
    int e = blockIdx.x * blockDim.x + threadIdx.x;
    if (e >= EE) return;
    int p = atomicAdd(&cur[dst[e]], 1);
    srcp[p] = src[e];
}

// ---------------- bf16 helpers ----------------
__device__ __forceinline__ void split2_bf16(float x, float y,
                                            uint32_t& h, uint32_t& l) {
    __nv_bfloat162 hh = __floats2bfloat162_rn(x, y);
    h = *(uint32_t*)&hh;
    float rx = x - __bfloat162float(hh.x);
    float ry = y - __bfloat162float(hh.y);
    __nv_bfloat162 ll = __floats2bfloat162_rn(rx, ry);
    l = *(uint32_t*)&ll;
}

__device__ __forceinline__ void mma_bf16(float* c, uint32_t a0, uint32_t a1,
                                         uint32_t a2, uint32_t a3,
                                         uint32_t b0, uint32_t b1) {
    asm volatile(
        "mma.sync.aligned.m16n8k16.row.col.f32.bf16.bf16.f32 "
        "{%0,%1,%2,%3}, {%4,%5,%6,%7}, {%8,%9}, {%0,%1,%2,%3};"
        : "+f"(c[0]), "+f"(c[1]), "+f"(c[2]), "+f"(c[3])
        : "r"(a0), "r"(a1), "r"(a2), "r"(a3), "r"(b0), "r"(b1));
}

// ---------------- one-time weight split: [K][M] f32 -> [M][K/2] bf16x2 ------
__global__ void split_wb_k(const float* __restrict__ W1,
                           const float* __restrict__ W2,
                           const float* __restrict__ W3,
                           uint32_t* __restrict__ wbh,
                           uint32_t* __restrict__ wbl) {
    int i = blockIdx.x * blockDim.x + threadIdx.x;
    if (i >= WBTOT) return;
    const float* W; int K, M, idx;
    if (i < WB2)      { W = W1; K = IN_DIM; M = HID;  idx = i; }
    else if (i < WB3) { W = W2; K = HID;    M = HID;  idx = i - WB2; }
    else              { W = W3; K = HID;    M = OUTD; idx = i - WB3; }
    int kb2 = K / 2;
    int n = idx / kb2;
    int j = idx - n * kb2;
    float x = W[(size_t)(2 * j) * M + n];
    float y = W[(size_t)(2 * j + 1) * M + n];
    uint32_t h, l;
    split2_bf16(x, y, h, l);
    wbh[i] = h;
    wbl[i] = l;
}

// ---------------- GEMM + fused logit epilogue, 3xBF16 ----------------
// C[N,M] = A[N,K](lda) * B[K,M]; also as/ad += C . a_src/a_dst per head.
// INHALF: A is fp16 (fp16->2xbf16 split is exact). C stored fp16 always.
#define PITCH 20
#define GEMM_SMEM (4 * 128 * PITCH * 4)
template<int INHALF>
__global__ __launch_bounds__(256, 2)
void gemm_tc_k(const void* __restrict__ Av, int lda,
               const uint32_t* __restrict__ Bhg,
               const uint32_t* __restrict__ Blg,
               __half* __restrict__ C,
               int Nrows, int K, int M,
               const float* __restrict__ a_src,
               const float* __restrict__ a_dst,
               float* __restrict__ as_, float* __restrict__ ad_) {
    extern __shared__ uint32_t smem[];
    uint32_t (*Ah)[PITCH] = (uint32_t(*)[PITCH])smem;
    uint32_t (*Al)[PITCH] = (uint32_t(*)[PITCH])(smem + 128 * PITCH);
    uint32_t (*Bh)[PITCH] = (uint32_t(*)[PITCH])(smem + 2 * 128 * PITCH);
    uint32_t (*Bl)[PITCH] = (uint32_t(*)[PITCH])(smem + 3 * 128 * PITCH);

    const int tid = threadIdx.x;
    const int wid = tid >> 5;
    const int lane = tid & 31;
    const int gid = lane >> 2;
    const int t4 = lane & 3;
    const int rm = blockIdx.y * 128;
    const int cn = blockIdx.x * 128;
    const int wm = (wid & 1) * 64;
    const int wn = (wid >> 1) * 32;
    const int KB2 = K >> 1;

    float acc[4][4][4];
#pragma unroll
    for (int i = 0; i < 4; i++)
#pragma unroll
        for (int j = 0; j < 4; j++)
#pragma unroll
            for (int q = 0; q < 4; q++) acc[i][j][q] = 0.f;

    const int ar = tid >> 3;
    const int af = tid & 7;
    const int bn2 = tid >> 1;
    const int bq = (tid & 1) * 2;

    for (int k0 = 0; k0 < K; k0 += 32) {
#pragma unroll
        for (int l = 0; l < 4; l++) {
            int row = ar + 32 * l;
            int grow = rm + row;
            float4 v = make_float4(0.f, 0.f, 0.f, 0.f);
            if (grow < Nrows) {
                if (INHALF) {
                    const __half* Ahalf = (const __half*)Av;
                    uint2 u = *(const uint2*)(Ahalf + (size_t)grow * lda + k0 + af * 4);
                    float2 f0 = __half22float2(*(const __half2*)&u.x);
                    float2 f1 = __half22float2(*(const __half2*)&u.y);
                    v = make_float4(f0.x, f0.y, f1.x, f1.y);
                } else {
                    const float* Af = (const float*)Av;
                    v = *(const float4*)(Af + (size_t)grow * lda + k0 + af * 4);
                }
            }
            uint32_t h0, l0, h1, l1;
            split2_bf16(v.x, v.y, h0, l0);
            split2_bf16(v.z, v.w, h1, l1);
            Ah[row][af * 2] = h0; Ah[row][af * 2 + 1] = h1;
            Al[row][af * 2] = l0; Al[row][af * 2 + 1] = l1;
        }
#pragma unroll
        for (int u = 0; u < 2; u++) {
            int q = bq + u;
            size_t go = (size_t)(cn + bn2) * KB2 + (k0 >> 1) + q * 4;
            *(uint4*)&Bh[bn2][q * 4] = *(const uint4*)(Bhg + go);
            *(uint4*)&Bl[bn2][q * 4] = *(const uint4*)(Blg + go);
        }
        __syncthreads();

#pragma unroll
        for (int s = 0; s < 2; s++) {
            const int jb = s * 8;
            uint32_t ah[4][4], al[4][4], bh[4][2], bl[4][2];
#pragma unroll
            for (int ma = 0; ma < 4; ma++) {
                int m = wm + ma * 16;
                ah[ma][0] = Ah[m + gid][jb + t4];
                ah[ma][1] = Ah[m + gid + 8][jb + t4];
                ah[ma][2] = Ah[m + gid][jb + t4 + 4];
                ah[ma][3] = Ah[m + gid + 8][jb + t4 + 4];
                al[ma][0] = Al[m + gid][jb + t4];
                al[ma][1] = Al[m + gid + 8][jb + t4];
                al[ma][2] = Al[m + gid][jb + t4 + 4];
                al[ma][3] = Al[m + gid + 8][jb + t4 + 4];
            }
#pragma unroll
            for (int nb = 0; nb < 4; nb++) {
                int col = wn + nb * 8 + gid;
                bh[nb][0] = Bh[col][jb + t4];
                bh[nb][1] = Bh[col][jb + t4 + 4];
                bl[nb][0] = Bl[col][jb + t4];
                bl[nb][1] = Bl[col][jb + t4 + 4];
            }
#pragma unroll
            for (int ma = 0; ma < 4; ma++)
#pragma unroll
                for (int nb = 0; nb < 4; nb++) {
                    float* c = acc[ma][nb];
                    mma_bf16(c, ah[ma][0], ah[ma][1], ah[ma][2], ah[ma][3],
                             bh[nb][0], bh[nb][1]);
                    mma_bf16(c, ah[ma][0], ah[ma][1], ah[ma][2], ah[ma][3],
                             bl[nb][0], bl[nb][1]);
                    mma_bf16(c, al[ma][0], al[ma][1], al[ma][2], al[ma][3],
                             bh[nb][0], bh[nb][1]);
                }
        }
        __syncthreads();
    }

    // ---- store C (fp16) ----
#pragma unroll
    for (int ma = 0; ma < 4; ma++) {
        int r0 = rm + wm + ma * 16 + gid;
        int r1 = r0 + 8;
#pragma unroll
        for (int nb = 0; nb < 4; nb++) {
            int col = cn + wn + nb * 8 + 2 * t4;
            if (r0 < Nrows)
                *(__half2*)(C + (size_t)r0 * M + col) =
                    __floats2half2_rn(acc[ma][nb][0], acc[ma][nb][1]);
            if (r1 < Nrows)
                *(__half2*)(C + (size_t)r1 * M + col) =
                    __floats2half2_rn(acc[ma][nb][2], acc[ma][nb][3]);
        }
    }

    // ---- fused logit epilogue (fp32 accumulators -> exact logits) ----
    const int head = (cn + wn) / (M / 4);
    float av[4][2], dv[4][2];
#pragma unroll
    for (int nb = 0; nb < 4; nb++)
#pragma unroll
        for (int q = 0; q < 2; q++) {
            int col = cn + wn + nb * 8 + 2 * t4 + q;
            av[nb][q] = __ldg(a_src + col);
            dv[nb][q] = __ldg(a_dst + col);
        }
#pragma unroll
    for (int ma = 0; ma < 4; ma++) {
#pragma unroll
        for (int r = 0; r < 2; r++) {
            float vs = 0.f, vd = 0.f;
#pragma unroll
            for (int nb = 0; nb < 4; nb++)
#pragma unroll
                for (int q = 0; q < 2; q++) {
                    float c = acc[ma][nb][r * 2 + q];
                    vs += c * av[nb][q];
                    vd += c * dv[nb][q];
                }
            vs += __shfl_xor_sync(0xffffffffu, vs, 1);
            vs += __shfl_xor_sync(0xffffffffu, vs, 2);
            vd += __shfl_xor_sync(0xffffffffu, vd, 1);
            vd += __shfl_xor_sync(0xffffffffu, vd, 2);
            int row = rm + wm + ma * 16 + gid + r * 8;
            if (t4 == 0 && row < Nrows) {
                atomicAdd(&as_[row * 4 + head], vs);
                atomicAdd(&ad_[row * 4 + head], vd);
            }
        }
    }
}

// ---------------- fused softmax + gather aggregation (warp per node) -------
// h table fp16 always; OUTHALF: write out fp16 (intermediate) vs fp32 (final)
template<int M, int DORELU, int OUTHALF>
__global__ void gat_node_k(const int* __restrict__ roff,
                           const int* __restrict__ srcp,
                           const float* __restrict__ as_,
                           const float* __restrict__ ad_,
                           const __half* __restrict__ hw,
                           float* __restrict__ wbuf,
                           const float* __restrict__ bias,
                           void* __restrict__ outv, int ostride) {
    constexpr int NC = M / 32;
    int warp = (blockIdx.x * blockDim.x + threadIdx.x) >> 5;
    int lane = threadIdx.x & 31;
    if (warp >= NN) return;
    const int n = warp;
    const int beg = roff[n], end = roff[n + 1];
    const int h = lane & 3, slot = lane >> 2;

    float adv = ad_[n * 4 + h];
    float mx = -CUDART_INF_F;
    for (int i = beg + slot; i < end; i += 8) {
        int s = srcp[i];
        float v = as_[s * 4 + h] + adv;
        v = (v > 0.f) ? v : NEG * v;
        wbuf[(size_t)i * 4 + h] = v;
        mx = fmaxf(mx, v);
    }
    mx = fmaxf(mx, __shfl_xor_sync(0xffffffffu, mx, 4));
    mx = fmaxf(mx, __shfl_xor_sync(0xffffffffu, mx, 8));
    mx = fmaxf(mx, __shfl_xor_sync(0xffffffffu, mx, 16));

    float den = 0.f;
    for (int i = beg + slot; i < end; i += 8) {
        float w = expf(wbuf[(size_t)i * 4 + h] - mx);
        wbuf[(size_t)i * 4 + h] = w;
        den += w;
    }
    den += __shfl_xor_sync(0xffffffffu, den, 4);
    den += __shfl_xor_sync(0xffffffffu, den, 8);
    den += __shfl_xor_sync(0xffffffffu, den, 16);
    den += 1e-16f;
    __threadfence_block();
    __syncwarp();

    const int hh = lane >> 3;
    float dinv = 1.0f / __shfl_sync(0xffffffffu, den, hh);
    float acc[NC];
#pragma unroll
    for (int j = 0; j < NC; j++) acc[j] = 0.f;
    const int colbase = lane * NC;
    for (int i = beg; i < end; i++) {
        int s = srcp[i];
        float4 w4 = *(const float4*)(wbuf + (size_t)i * 4);
        float wv = (hh == 0) ? w4.x : (hh == 1) ? w4.y : (hh == 2) ? w4.z : w4.w;
        float a = wv * dinv;
        const __half* hp = hw + (size_t)s * M + colbase;
        if (NC == 8) {
            uint4 u = *(const uint4*)hp;
            float2 f0 = __half22float2(*(const __half2*)&u.x);
            float2 f1 = __half22float2(*(const __half2*)&u.y);
            float2 f2 = __half22float2(*(const __half2*)&u.z);
            float2 f3 = __half22float2(*(const __half2*)&u.w);
            acc[0] += a * f0.x; acc[1] += a * f0.y;
            acc[2] += a * f1.x; acc[3] += a * f1.y;
            acc[4] += a * f2.x; acc[5] += a * f2.y;
            acc[6] += a * f3.x; acc[7 % NC] += a * f3.y;
        } else {
            uint2 u = *(const uint2*)hp;
            float2 f0 = __half22float2(*(const __half2*)&u.x);
            float2 f1 = __half22float2(*(const __half2*)&u.y);
            acc[0] += a * f0.x; acc[1] += a * f0.y;
            acc[2 % NC] += a * f1.x; acc[3 % NC] += a * f1.y;
        }
    }
    const float* bp = bias + colbase;
    if (OUTHALF) {
        __half* op = (__half*)outv + (size_t)n * ostride + colbase;
#pragma unroll
        for (int j = 0; j < NC; j += 2) {
            float v0 = acc[j] + bp[j];
            float v1 = acc[j + 1] + bp[j + 1];
            if (DORELU) { v0 = fmaxf(v0, 0.f); v1 = fmaxf(v1, 0.f); }
            *(__half2*)(op + j) = __floats2half2_rn(v0, v1);
        }
    } else {
        float* op = (float*)outv + (size_t)n * ostride + colbase;
#pragma unroll
        for (int j = 0; j < NC; j++) {
            float v = acc[j] + bp[j];
            if (DORELU) v = fmaxf(v, 0.f);
            op[j] = v;
        }
    }
}

// ---------------- host orchestration ----------------
extern "C" void kernel_launch(void* const* d_in, const int* in_sizes, int n_in,
                              void* d_out, int out_size) {
    const float* x  = (const float*)d_in[0];
    const void*  ei = d_in[1];
    const float* asrc[3] = {(const float*)d_in[3], (const float*)d_in[7],
                            (const float*)d_in[11]};
    const float* adst[3] = {(const float*)d_in[4], (const float*)d_in[8],
                            (const float*)d_in[12]};
    const float* bias[3] = {(const float*)d_in[5], (const float*)d_in[9],
                            (const float*)d_in[13]};
    float* out = (float*)d_out;

    static cudaStream_t ss[NCHAIN - 1];
    static cudaEvent_t ev_fork, ev_join[NCHAIN - 1];
    static bool inited = false;
    if (!inited) {
        inited = true;
        for (int i = 0; i < NCHAIN - 1; i++) {
            cudaStreamCreateWithFlags(&ss[i], cudaStreamNonBlocking);
            cudaEventCreateWithFlags(&ev_join[i], cudaEventDisableTiming);
        }
        cudaEventCreateWithFlags(&ev_fork, cudaEventDisableTiming);
        cudaFuncSetAttribute(gemm_tc_k<0>,
                             cudaFuncAttributeMaxDynamicSharedMemorySize,
                             GEMM_SMEM);
        cudaFuncSetAttribute(gemm_tc_k<1>,
                             cudaFuncAttributeMaxDynamicSharedMemorySize,
                             GEMM_SMEM);
    }

    __half *p_hw[NCHAIN], *p_x[NCHAIN];
    float *p_w[NCHAIN], *p_asd[NCHAIN];
    {
        float4 *b_hw, *b_x, *b_w; float *b_asd;
        cudaGetSymbolAddress((void**)&b_hw, g_hw4);
        cudaGetSymbolAddress((void**)&b_x, g_x4);
        cudaGetSymbolAddress((void**)&b_w, g_w4);
        cudaGetSymbolAddress((void**)&b_asd, g_asd);
        for (int c = 0; c < NCHAIN; c++) {
            p_hw[c]  = (__half*)(b_hw + (size_t)c * (NN * HID / 4));
            p_x[c]   = (__half*)(b_x  + (size_t)c * (NN * HID / 4));
            p_w[c]   = (float*)(b_w  + (size_t)c * EE);
            p_asd[c] = b_asd + (size_t)c * (2 * NN * HEADS);
        }
    }
    uint32_t *p_wbh, *p_wbl;
    cudaGetSymbolAddress((void**)&p_wbh, g_wbh);
    cudaGetSymbolAddress((void**)&p_wbl, g_wbl);
    int *p_src, *p_dst, *p_cnt, *p_roff, *p_cur, *p_srcp;
    cudaGetSymbolAddress((void**)&p_src, g_src);
    cudaGetSymbolAddress((void**)&p_dst, g_dst);
    cudaGetSymbolAddress((void**)&p_cnt, g_cnt);
    cudaGetSymbolAddress((void**)&p_roff, g_roff);
    cudaGetSymbolAddress((void**)&p_cur, g_cur);
    cudaGetSymbolAddress((void**)&p_srcp, g_srcp);

    const uint32_t* wbh[3] = {p_wbh + WB1, p_wbh + WB2, p_wbh + WB3};
    const uint32_t* wbl[3] = {p_wbl + WB1, p_wbl + WB2, p_wbl + WB3};

    // --- preprocessing on stream 0 ---
    detconv_k<<<(EE + 255) / 256, 256>>>(ei);
    hist_k<<<(EE + 255) / 256, 256>>>(p_dst, p_cnt);
    scan_k<<<1, 1024>>>(p_cnt, p_roff, p_cur);
    scatter_k<<<(EE + 255) / 256, 256>>>(p_src, p_dst, p_cur, p_srcp);
    split_wb_k<<<(WBTOT + 255) / 256, 256>>>((const float*)d_in[2],
                                             (const float*)d_in[6],
                                             (const float*)d_in[10],
                                             p_wbh, p_wbl);

    cudaEventRecord(ev_fork, 0);
    for (int i = 0; i < NCHAIN - 1; i++)
        cudaStreamWaitEvent(ss[i], ev_fork, 0);

    const int npblk = (NN * 32 + 255) / 256;
    const int rowblk = (NN + 127) / 128;

    for (int c = 0; c < NCHAIN; c++) {
        cudaStream_t st = (c == 0) ? (cudaStream_t)0 : ss[c - 1];
        float* as_ = p_asd[c];
        float* ad_ = p_asd[c] + NN * HEADS;
        for (int t = c; t < TT; t += NCHAIN) {
            // layer 1: fp32 in -> fp16 h -> fp16 x
            {
                cudaMemsetAsync(p_asd[c], 0, 2 * NN * HEADS * sizeof(float), st);
                dim3 gg(HID / 128, rowblk);
                gemm_tc_k<0><<<gg, 256, GEMM_SMEM, st>>>(
                    x + (size_t)t * IN_DIM, TT * IN_DIM, wbh[0], wbl[0],
                    p_hw[c], NN, IN_DIM, HID, asrc[0], adst[0], as_, ad_);
                gat_node_k<HID, 1, 1><<<npblk, 256, 0, st>>>(
                    p_roff, p_srcp, as_, ad_, p_hw[c], p_w[c],
                    bias[0], p_x[c], HID);
            }
            // layer 2: fp16 in -> fp16 h -> fp16 x
            {
                cudaMemsetAsync(p_asd[c], 0, 2 * NN * HEADS * sizeof(float), st);
                dim3 gg(HID / 128, rowblk);
                gemm_tc_k<1><<<gg, 256, GEMM_SMEM, st>>>(
                    p_x[c], HID, wbh[1], wbl[1], p_hw[c], NN, HID, HID,
                    asrc[1], adst[1], as_, ad_);
                gat_node_k<HID, 1, 1><<<npblk, 256, 0, st>>>(
                    p_roff, p_srcp, as_, ad_, p_hw[c], p_w[c],
                    bias[1], p_x[c], HID);
            }
            // layer 3: fp16 in -> fp16 h -> fp32 out
            {
                cudaMemsetAsync(p_asd[c], 0, 2 * NN * HEADS * sizeof(float), st);
                dim3 gg(OUTD / 128, rowblk);
                gemm_tc_k<1><<<gg, 256, GEMM_SMEM, st>>>(
                    p_x[c], HID, wbh[2], wbl[2], p_hw[c], NN, HID, OUTD,
                    asrc[2], adst[2], as_, ad_);
                gat_node_k<OUTD, 0, 0><<<npblk, 256, 0, st>>>(
                    p_roff, p_srcp, as_, ad_, p_hw[c], p_w[c],
                    bias[2], out + (size_t)t * OUTD, TT * OUTD);
            }
        }
    }

    for (int i = 0; i < NCHAIN - 1; i++) {
        cudaEventRecord(ev_join[i], ss[i]);
        cudaStreamWaitEvent((cudaStream_t)0, ev_join[i], 0);
    }
}

// round 16
// speedup vs baseline: 1.6882x; 1.0553x over previous
#include <cuda_runtime.h>
#include <cuda_bf16.h>
#include <cuda_fp16.h>
#include <math_constants.h>
#include <cstdint>

// ---------------- problem constants ----------------
#define NN      20000
#define EE      320000
#define TT      12
#define IN_DIM  128
#define HID     256
#define OUTD    128
#define HEADS   4
#define NEG     0.2f
#define NCHAIN  4            // 3 extra streams max (R11: more trips alloc guard)
#define NEGBIG  (-1.0e30f)   // finite -inf substitute (R15 NaN lesson)

// packed bf16 weight tables, layout [M][K/2] u32
#define WB1 0
#define WB2 16384
#define WB3 49152
#define WBTOT 65536

// ---------------- device scratch (per-chain) ----------------
__device__ float4   g_hw4[NCHAIN][(size_t)NN * HID / 4];   // h (fp16)
__device__ float4   g_x4 [NCHAIN][(size_t)NN * HID / 4];   // x (fp16)
__device__ float4   g_w4 [NCHAIN][EE + 8];                 // logits (padded)
__device__ float    g_asd[NCHAIN][2 * NN * HEADS];
__device__ uint32_t g_wbh[WBTOT];
__device__ uint32_t g_wbl[WBTOT];
__device__ int      g_src [EE];
__device__ int      g_dst [EE];
__device__ int      g_cnt [NN];
__device__ int      g_roff[NN + 1];
__device__ int      g_cur [NN];
__device__ int      g_srcp[EE + 8];

// ---------------- edge-index dtype detect + normalize (+ cnt zero) ---------
__global__ void detconv_k(const void* ei) {
    __shared__ int is64;
    if (threadIdx.x == 0) {
        int bad = 0;
        const long long* p = (const long long*)ei;
        for (int i = 0; i < 256; i++) {
            long long v = p[i];
            if (v < 0 || v >= NN) { bad = 1; break; }
        }
        is64 = bad ? 0 : 1;
    }
    __syncthreads();
    int i = blockIdx.x * blockDim.x + threadIdx.x;
    if (i < NN) g_cnt[i] = 0;
    if (i >= EE) return;
    if (is64) {
        const long long* p = (const long long*)ei;
        g_src[i] = (int)p[i];
        g_dst[i] = (int)p[EE + i];
    } else {
        const int* p = (const int*)ei;
        g_src[i] = p[i];
        g_dst[i] = p[EE + i];
    }
}

// ---------------- CSR build (by dst) ----------------
__global__ void hist_k(const int* __restrict__ dst, int* __restrict__ cnt) {
    int e = blockIdx.x * blockDim.x + threadIdx.x;
    if (e < EE) atomicAdd(&cnt[dst[e]], 1);
}

__global__ void scan_k(const int* __restrict__ cnt, int* __restrict__ roff,
                       int* __restrict__ cur) {
    __shared__ int part[1024];
    const int chunk = (NN + 1023) / 1024;
    int t = threadIdx.x;
    int lo = t * chunk;
    int hi = lo + chunk; if (hi > NN) hi = NN;
    int s = 0;
    for (int i = lo; i < hi; i++) s += cnt[i];
    part[t] = s;
    __syncthreads();
    for (int o = 1; o < 1024; o <<= 1) {
        int v = (t >= o) ? part[t - o] : 0;
        __syncthreads();
        part[t] += v;
        __syncthreads();
    }
    int base = (t == 0) ? 0 : part[t - 1];
    for (int i = lo; i < hi; i++) {
        roff[i] = base;
        cur[i] = base;
        base += cnt[i];
    }
    if (t == 1023) roff[NN] = base;
}

__global__ void scatter_k(const int* __restrict__ src,
                          const int* __restrict__ dst,
                          int* __restrict__ cur, int* __restrict__ srcp) {
    int e = blockIdx.x * blockDim.x + threadIdx.x;
    if (e >= EE) return;
    int p = atomicAdd(&cur[dst[e]], 1);
    srcp[p] = src[e];
}

// ---------------- bf16 helpers ----------------
__device__ __forceinline__ void split2_bf16(float x, float y,
                                            uint32_t& h, uint32_t& l) {
    __nv_bfloat162 hh = __floats2bfloat162_rn(x, y);
    h = *(uint32_t*)&hh;
    float rx = x - __bfloat162float(hh.x);
    float ry = y - __bfloat162float(hh.y);
    __nv_bfloat162 ll = __floats2bfloat162_rn(rx, ry);
    l = *(uint32_t*)&ll;
}

__device__ __forceinline__ void mma_bf16(float* c, uint32_t a0, uint32_t a1,
                                         uint32_t a2, uint32_t a3,
                                         uint32_t b0, uint32_t b1) {
    asm volatile(
        "mma.sync.aligned.m16n8k16.row.col.f32.bf16.bf16.f32 "
        "{%0,%1,%2,%3}, {%4,%5,%6,%7}, {%8,%9}, {%0,%1,%2,%3};"
        : "+f"(c[0]), "+f"(c[1]), "+f"(c[2]), "+f"(c[3])
        : "r"(a0), "r"(a1), "r"(a2), "r"(a3), "r"(b0), "r"(b1));
}

// ---------------- one-time weight split: [K][M] f32 -> [M][K/2] bf16x2 ------
__global__ void split_wb_k(const float* __restrict__ W1,
                           const float* __restrict__ W2,
                           const float* __restrict__ W3,
                           uint32_t* __restrict__ wbh,
                           uint32_t* __restrict__ wbl) {
    int i = blockIdx.x * blockDim.x + threadIdx.x;
    if (i >= WBTOT) return;
    const float* W; int K, M, idx;
    if (i < WB2)      { W = W1; K = IN_DIM; M = HID;  idx = i; }
    else if (i < WB3) { W = W2; K = HID;    M = HID;  idx = i - WB2; }
    else              { W = W3; K = HID;    M = OUTD; idx = i - WB3; }
    int kb2 = K / 2;
    int n = idx / kb2;
    int j = idx - n * kb2;
    float x = W[(size_t)(2 * j) * M + n];
    float y = W[(size_t)(2 * j + 1) * M + n];
    uint32_t h, l;
    split2_bf16(x, y, h, l);
    wbh[i] = h;
    wbl[i] = l;
}

// ---------------- GEMM + fused logit epilogue, 3xBF16 ----------------
#define PITCH 20
#define GEMM_SMEM (4 * 128 * PITCH * 4)
template<int INHALF>
__global__ __launch_bounds__(256, 2)
void gemm_tc_k(const void* __restrict__ Av, int lda,
               const uint32_t* __restrict__ Bhg,
               const uint32_t* __restrict__ Blg,
               __half* __restrict__ C,
               int Nrows, int K, int M,
               const float* __restrict__ a_src,
               const float* __restrict__ a_dst,
               float* __restrict__ as_, float* __restrict__ ad_) {
    extern __shared__ uint32_t smem[];
    uint32_t (*Ah)[PITCH] = (uint32_t(*)[PITCH])smem;
    uint32_t (*Al)[PITCH] = (uint32_t(*)[PITCH])(smem + 128 * PITCH);
    uint32_t (*Bh)[PITCH] = (uint32_t(*)[PITCH])(smem + 2 * 128 * PITCH);
    uint32_t (*Bl)[PITCH] = (uint32_t(*)[PITCH])(smem + 3 * 128 * PITCH);

    const int tid = threadIdx.x;
    const int wid = tid >> 5;
    const int lane = tid & 31;
    const int gid = lane >> 2;
    const int t4 = lane & 3;
    const int rm = blockIdx.y * 128;
    const int cn = blockIdx.x * 128;
    const int wm = (wid & 1) * 64;
    const int wn = (wid >> 1) * 32;
    const int KB2 = K >> 1;

    float acc[4][4][4];
#pragma unroll
    for (int i = 0; i < 4; i++)
#pragma unroll
        for (int j = 0; j < 4; j++)
#pragma unroll
            for (int q = 0; q < 4; q++) acc[i][j][q] = 0.f;

    const int ar = tid >> 3;
    const int af = tid & 7;
    const int bn2 = tid >> 1;
    const int bq = (tid & 1) * 2;

    for (int k0 = 0; k0 < K; k0 += 32) {
#pragma unroll
        for (int l = 0; l < 4; l++) {
            int row = ar + 32 * l;
            int grow = rm + row;
            float4 v = make_float4(0.f, 0.f, 0.f, 0.f);
            if (grow < Nrows) {
                if (INHALF) {
                    const __half* Ahalf = (const __half*)Av;
                    uint2 u = *(const uint2*)(Ahalf + (size_t)grow * lda + k0 + af * 4);
                    float2 f0 = __half22float2(*(const __half2*)&u.x);
                    float2 f1 = __half22float2(*(const __half2*)&u.y);
                    v = make_float4(f0.x, f0.y, f1.x, f1.y);
                } else {
                    const float* Af = (const float*)Av;
                    v = *(const float4*)(Af + (size_t)grow * lda + k0 + af * 4);
                }
            }
            uint32_t h0, l0, h1, l1;
            split2_bf16(v.x, v.y, h0, l0);
            split2_bf16(v.z, v.w, h1, l1);
            Ah[row][af * 2] = h0; Ah[row][af * 2 + 1] = h1;
            Al[row][af * 2] = l0; Al[row][af * 2 + 1] = l1;
        }
#pragma unroll
        for (int u = 0; u < 2; u++) {
            int q = bq + u;
            size_t go = (size_t)(cn + bn2) * KB2 + (k0 >> 1) + q * 4;
            *(uint4*)&Bh[bn2][q * 4] = *(const uint4*)(Bhg + go);
            *(uint4*)&Bl[bn2][q * 4] = *(const uint4*)(Blg + go);
        }
        __syncthreads();

#pragma unroll
        for (int s = 0; s < 2; s++) {
            const int jb = s * 8;
            uint32_t ah[4][4], al[4][4], bh[4][2], bl[4][2];
#pragma unroll
            for (int ma = 0; ma < 4; ma++) {
                int m = wm + ma * 16;
                ah[ma][0] = Ah[m + gid][jb + t4];
                ah[ma][1] = Ah[m + gid + 8][jb + t4];
                ah[ma][2] = Ah[m + gid][jb + t4 + 4];
                ah[ma][3] = Ah[m + gid + 8][jb + t4 + 4];
                al[ma][0] = Al[m + gid][jb + t4];
                al[ma][1] = Al[m + gid + 8][jb + t4];
                al[ma][2] = Al[m + gid][jb + t4 + 4];
                al[ma][3] = Al[m + gid + 8][jb + t4 + 4];
            }
#pragma unroll
            for (int nb = 0; nb < 4; nb++) {
                int col = wn + nb * 8 + gid;
                bh[nb][0] = Bh[col][jb + t4];
                bh[nb][1] = Bh[col][jb + t4 + 4];
                bl[nb][0] = Bl[col][jb + t4];
                bl[nb][1] = Bl[col][jb + t4 + 4];
            }
#pragma unroll
            for (int ma = 0; ma < 4; ma++)
#pragma unroll
                for (int nb = 0; nb < 4; nb++) {
                    float* c = acc[ma][nb];
                    mma_bf16(c, ah[ma][0], ah[ma][1], ah[ma][2], ah[ma][3],
                             bh[nb][0], bh[nb][1]);
                    mma_bf16(c, ah[ma][0], ah[ma][1], ah[ma][2], ah[ma][3],
                             bl[nb][0], bl[nb][1]);
                    mma_bf16(c, al[ma][0], al[ma][1], al[ma][2], al[ma][3],
                             bh[nb][0], bh[nb][1]);
                }
        }
        __syncthreads();
    }

    // ---- store C (fp16) ----
#pragma unroll
    for (int ma = 0; ma < 4; ma++) {
        int r0 = rm + wm + ma * 16 + gid;
        int r1 = r0 + 8;
#pragma unroll
        for (int nb = 0; nb < 4; nb++) {
            int col = cn + wn + nb * 8 + 2 * t4;
            if (r0 < Nrows)
                *(__half2*)(C + (size_t)r0 * M + col) =
                    __floats2half2_rn(acc[ma][nb][0], acc[ma][nb][1]);
            if (r1 < Nrows)
                *(__half2*)(C + (size_t)r1 * M + col) =
                    __floats2half2_rn(acc[ma][nb][2], acc[ma][nb][3]);
        }
    }

    // ---- fused logit epilogue ----
    const int head = (cn + wn) / (M / 4);
    float av[4][2], dv[4][2];
#pragma unroll
    for (int nb = 0; nb < 4; nb++)
#pragma unroll
        for (int q = 0; q < 2; q++) {
            int col = cn + wn + nb * 8 + 2 * t4 + q;
            av[nb][q] = __ldg(a_src + col);
            dv[nb][q] = __ldg(a_dst + col);
        }
#pragma unroll
    for (int ma = 0; ma < 4; ma++) {
#pragma unroll
        for (int r = 0; r < 2; r++) {
            float vs = 0.f, vd = 0.f;
#pragma unroll
            for (int nb = 0; nb < 4; nb++)
#pragma unroll
                for (int q = 0; q < 2; q++) {
                    float c = acc[ma][nb][r * 2 + q];
                    vs += c * av[nb][q];
                    vd += c * dv[nb][q];
                }
            vs += __shfl_xor_sync(0xffffffffu, vs, 1);
            vs += __shfl_xor_sync(0xffffffffu, vs, 2);
            vd += __shfl_xor_sync(0xffffffffu, vd, 1);
            vd += __shfl_xor_sync(0xffffffffu, vd, 2);
            int row = rm + wm + ma * 16 + gid + r * 8;
            if (t4 == 0 && row < Nrows) {
                atomicAdd(&as_[row * 4 + head], vs);
                atomicAdd(&ad_[row * 4 + head], vd);
            }
        }
    }
}

// ---------------- fused softmax + gather (warp per node, 2-pass) -----------
template<int M, int DORELU, int OUTHALF>
__global__ void gat_node_k(const int* __restrict__ roff,
                           const int* __restrict__ srcp,
                           const float* __restrict__ as_,
                           const float* __restrict__ ad_,
                           const __half* __restrict__ hw,
                           float* __restrict__ wbuf,
                           const float* __restrict__ bias,
                           void* __restrict__ outv, int ostride) {
    constexpr int NC = M / 32;
    int warp = (blockIdx.x * blockDim.x + threadIdx.x) >> 5;
    int lane = threadIdx.x & 31;
    if (warp >= NN) return;
    const int n = warp;
    const int beg = roff[n], end = roff[n + 1];
    const int h = lane & 3, slot = lane >> 2;
    const int hh = lane >> 3;

    // ---- pass A: logits + online softmax stats (finite init: no NaN) ----
    float adv = ad_[n * 4 + h];
    float m = NEGBIG, s = 0.f;
    for (int i = beg + slot; i < end; i += 8) {
        int sn = srcp[i];
        float v = as_[sn * 4 + h] + adv;
        v = (v > 0.f) ? v : NEG * v;
        wbuf[(size_t)i * 4 + h] = v;
        if (v <= m) {
            s += expf(v - m);
        } else {
            s = s * expf(m - v) + 1.f;
            m = v;
        }
    }
#pragma unroll
    for (int o = 4; o <= 16; o <<= 1) {
        float mo = __shfl_xor_sync(0xffffffffu, m, o);
        float so = __shfl_xor_sync(0xffffffffu, s, o);
        float mn = fmaxf(m, mo);
        s = s * expf(m - mn) + so * expf(mo - mn);
        m = mn;
    }
    float dinv = 1.0f / (s + 1e-16f);
    __threadfence_block();
    __syncwarp();

    // ---- pass B: grouped gather, 8 edges per group, shuffle-distributed ----
    float acc[NC];
#pragma unroll
    for (int j = 0; j < NC; j++) acc[j] = 0.f;
    const int colbase = lane * NC;

    for (int i0 = beg; i0 < end; i0 += 8) {
        int ii = i0 + (lane >> 2);
        int sv = 0;
        float aval = 0.f;
        if (ii < end) {
            sv = srcp[ii];
            float v = wbuf[(size_t)i0 * 4 + lane];  // == wbuf[ii*4 + h]
            aval = expf(v - m) * dinv;
        }
        int lim = end - i0;
        if (lim > 8) lim = 8;
        if (lim == 8) {
#pragma unroll
            for (int j = 0; j < 8; j++) {
                float a = __shfl_sync(0xffffffffu, aval, (j << 2) | hh);
                int sg = __shfl_sync(0xffffffffu, sv, j << 2);
                const __half* hp = hw + (size_t)sg * M + colbase;
                if (NC == 8) {
                    uint4 u = *(const uint4*)hp;
                    float2 f0 = __half22float2(*(const __half2*)&u.x);
                    float2 f1 = __half22float2(*(const __half2*)&u.y);
                    float2 f2 = __half22float2(*(const __half2*)&u.z);
                    float2 f3 = __half22float2(*(const __half2*)&u.w);
                    acc[0] += a * f0.x; acc[1] += a * f0.y;
                    acc[2] += a * f1.x; acc[3] += a * f1.y;
                    acc[4] += a * f2.x; acc[5] += a * f2.y;
                    acc[6] += a * f3.x; acc[7 % NC] += a * f3.y;
                } else {
                    uint2 u = *(const uint2*)hp;
                    float2 f0 = __half22float2(*(const __half2*)&u.x);
                    float2 f1 = __half22float2(*(const __half2*)&u.y);
                    acc[0] += a * f0.x; acc[1] += a * f0.y;
                    acc[2 % NC] += a * f1.x; acc[3 % NC] += a * f1.y;
                }
            }
        } else {
            for (int j = 0; j < lim; j++) {
                float a = __shfl_sync(0xffffffffu, aval, (j << 2) | hh);
                int sg = __shfl_sync(0xffffffffu, sv, j << 2);
                const __half* hp = hw + (size_t)sg * M + colbase;
                if (NC == 8) {
                    uint4 u = *(const uint4*)hp;
                    float2 f0 = __half22float2(*(const __half2*)&u.x);
                    float2 f1 = __half22float2(*(const __half2*)&u.y);
                    float2 f2 = __half22float2(*(const __half2*)&u.z);
                    float2 f3 = __half22float2(*(const __half2*)&u.w);
                    acc[0] += a * f0.x; acc[1] += a * f0.y;
                    acc[2] += a * f1.x; acc[3] += a * f1.y;
                    acc[4] += a * f2.x; acc[5] += a * f2.y;
                    acc[6] += a * f3.x; acc[7 % NC] += a * f3.y;
                } else {
                    uint2 u = *(const uint2*)hp;
                    float2 f0 = __half22float2(*(const __half2*)&u.x);
                    float2 f1 = __half22float2(*(const __half2*)&u.y);
                    acc[0] += a * f0.x; acc[1] += a * f0.y;
                    acc[2 % NC] += a * f1.x; acc[3 % NC] += a * f1.y;
                }
            }
        }
    }

    const float* bp = bias + colbase;
    if (OUTHALF) {
        __half* op = (__half*)outv + (size_t)n * ostride + colbase;
#pragma unroll
        for (int j = 0; j < NC; j += 2) {
            float v0 = acc[j] + bp[j];
            float v1 = acc[j + 1] + bp[j + 1];
            if (DORELU) { v0 = fmaxf(v0, 0.f); v1 = fmaxf(v1, 0.f); }
            *(__half2*)(op + j) = __floats2half2_rn(v0, v1);
        }
    } else {
        float* op = (float*)outv + (size_t)n * ostride + colbase;
#pragma unroll
        for (int j = 0; j < NC; j++) {
            float v = acc[j] + bp[j];
            if (DORELU) v = fmaxf(v, 0.f);
            op[j] = v;
        }
    }
}

// ---------------- host orchestration ----------------
extern "C" void kernel_launch(void* const* d_in, const int* in_sizes, int n_in,
                              void* d_out, int out_size) {
    const float* x  = (const float*)d_in[0];
    const void*  ei = d_in[1];
    const float* asrc[3] = {(const float*)d_in[3], (const float*)d_in[7],
                            (const float*)d_in[11]};
    const float* adst[3] = {(const float*)d_in[4], (const float*)d_in[8],
                            (const float*)d_in[12]};
    const float* bias[3] = {(const float*)d_in[5], (const float*)d_in[9],
                            (const float*)d_in[13]};
    float* out = (float*)d_out;

    static cudaStream_t ss[NCHAIN - 1];
    static cudaEvent_t ev_fork, ev_join[NCHAIN - 1];
    static bool inited = false;
    if (!inited) {
        inited = true;
        for (int i = 0; i < NCHAIN - 1; i++) {
            cudaStreamCreateWithFlags(&ss[i], cudaStreamNonBlocking);
            cudaEventCreateWithFlags(&ev_join[i], cudaEventDisableTiming);
        }
        cudaEventCreateWithFlags(&ev_fork, cudaEventDisableTiming);
        cudaFuncSetAttribute(gemm_tc_k<0>,
                             cudaFuncAttributeMaxDynamicSharedMemorySize,
                             GEMM_SMEM);
        cudaFuncSetAttribute(gemm_tc_k<1>,
                             cudaFuncAttributeMaxDynamicSharedMemorySize,
                             GEMM_SMEM);
    }

    __half *p_hw[NCHAIN], *p_x[NCHAIN];
    float *p_w[NCHAIN], *p_asd[NCHAIN];
    {
        float4 *b_hw, *b_x, *b_w; float *b_asd;
        cudaGetSymbolAddress((void**)&b_hw, g_hw4);
        cudaGetSymbolAddress((void**)&b_x, g_x4);
        cudaGetSymbolAddress((void**)&b_w, g_w4);
        cudaGetSymbolAddress((void**)&b_asd, g_asd);
        for (int c = 0; c < NCHAIN; c++) {
            p_hw[c]  = (__half*)(b_hw + (size_t)c * (NN * HID / 4));
            p_x[c]   = (__half*)(b_x  + (size_t)c * (NN * HID / 4));
            p_w[c]   = (float*)(b_w  + (size_t)c * (EE + 8));
            p_asd[c] = b_asd + (size_t)c * (2 * NN * HEADS);
        }
    }
    uint32_t *p_wbh, *p_wbl;
    cudaGetSymbolAddress((void**)&p_wbh, g_wbh);
    cudaGetSymbolAddress((void**)&p_wbl, g_wbl);
    int *p_src, *p_dst, *p_cnt, *p_roff, *p_cur, *p_srcp;
    cudaGetSymbolAddress((void**)&p_src, g_src);
    cudaGetSymbolAddress((void**)&p_dst, g_dst);
    cudaGetSymbolAddress((void**)&p_cnt, g_cnt);
    cudaGetSymbolAddress((void**)&p_roff, g_roff);
    cudaGetSymbolAddress((void**)&p_cur, g_cur);
    cudaGetSymbolAddress((void**)&p_srcp, g_srcp);

    const uint32_t* wbh[3] = {p_wbh + WB1, p_wbh + WB2, p_wbh + WB3};
    const uint32_t* wbl[3] = {p_wbl + WB1, p_wbl + WB2, p_wbl + WB3};

    // --- preprocessing on stream 0 ---
    detconv_k<<<(EE + 255) / 256, 256>>>(ei);
    hist_k<<<(EE + 255) / 256, 256>>>(p_dst, p_cnt);
    scan_k<<<1, 1024>>>(p_cnt, p_roff, p_cur);
    scatter_k<<<(EE + 255) / 256, 256>>>(p_src, p_dst, p_cur, p_srcp);
    split_wb_k<<<(WBTOT + 255) / 256, 256>>>((const float*)d_in[2],
                                             (const float*)d_in[6],
                                             (const float*)d_in[10],
                                             p_wbh, p_wbl);

    cudaEventRecord(ev_fork, 0);
    for (int i = 0; i < NCHAIN - 1; i++)
        cudaStreamWaitEvent(ss[i], ev_fork, 0);

    const int npblk = (NN * 32 + 255) / 256;
    const int rowblk = (NN + 127) / 128;

    for (int c = 0; c < NCHAIN; c++) {
        cudaStream_t st = (c == 0) ? (cudaStream_t)0 : ss[c - 1];
        float* as_ = p_asd[c];
        float* ad_ = p_asd[c] + NN * HEADS;
        for (int t = c; t < TT; t += NCHAIN) {
            // layer 1: fp32 in -> fp16 h -> fp16 x
            {
                cudaMemsetAsync(p_asd[c], 0, 2 * NN * HEADS * sizeof(float), st);
                dim3 gg(HID / 128, rowblk);
                gemm_tc_k<0><<<gg, 256, GEMM_SMEM, st>>>(
                    x + (size_t)t * IN_DIM, TT * IN_DIM, wbh[0], wbl[0],
                    p_hw[c], NN, IN_DIM, HID, asrc[0], adst[0], as_, ad_);
                gat_node_k<HID, 1, 1><<<npblk, 256, 0, st>>>(
                    p_roff, p_srcp, as_, ad_, p_hw[c], p_w[c],
                    bias[0], p_x[c], HID);
            }
            // layer 2: fp16 in -> fp16 h -> fp16 x
            {
                cudaMemsetAsync(p_asd[c], 0, 2 * NN * HEADS * sizeof(float), st);
                dim3 gg(HID / 128, rowblk);
                gemm_tc_k<1><<<gg, 256, GEMM_SMEM, st>>>(
                    p_x[c], HID, wbh[1], wbl[1], p_hw[c], NN, HID, HID,
                    asrc[1], adst[1], as_, ad_);
                gat_node_k<HID, 1, 1><<<npblk, 256, 0, st>>>(
                    p_roff, p_srcp, as_, ad_, p_hw[c], p_w[c],
                    bias[1], p_x[c], HID);
            }
            // layer 3: fp16 in -> fp16 h -> fp32 out
            {
                cudaMemsetAsync(p_asd[c], 0, 2 * NN * HEADS * sizeof(float), st);
                dim3 gg(OUTD / 128, rowblk);
                gemm_tc_k<1><<<gg, 256, GEMM_SMEM, st>>>(
                    p_x[c], HID, wbh[2], wbl[2], p_hw[c], NN, HID, OUTD,
                    asrc[2], adst[2], as_, ad_);
                gat_node_k<OUTD, 0, 0><<<npblk, 256, 0, st>>>(
                    p_roff, p_srcp, as_, ad_, p_hw[c], p_w[c],
                    bias[2], out + (size_t)t * OUTD, TT * OUTD);
            }
        }
    }

    for (int i = 0; i < NCHAIN - 1; i++) {
        cudaEventRecord(ev_join[i], ss[i]);
        cudaStreamWaitEvent((cudaStream_t)0, ev_join[i], 0);
    }
}